// round 2
// baseline (speedup 1.0000x reference)
#include <cuda_runtime.h>
#include <cstdint>

#define Bsz  128
#define Tseq 512
#define Din  512
#define Hdim 1024
#define BH   (Bsz * Hdim)
#define TBH  ((size_t)Tseq * (size_t)Bsz * (size_t)Hdim)   // 67,108,864
#define NC   128   // persistent CTAs

// ---------------- scratch (static device memory; no allocations) ----------------
__device__ float g_xproj[3ULL * 512ULL * 128ULL * 1024ULL]; // (gate, t, b, h) pre-activations
__device__ float g_hT [Hdim * Bsz];   // h transposed:  g_hT[k*128 + b]
__device__ float g_zT [Hdim * Bsz];   // z gate transposed
__device__ float g_rhT[Hdim * Bsz];   // (r * h) transposed
__device__ unsigned int g_bar = 0;    // monotonic grid-barrier counter

// packed fp32x2 FMA (sm_100+): d.lo += a.lo*b.lo ; d.hi += a.hi*b.hi
#define FMA2(d, a, b) asm("fma.rn.f32x2 %0, %1, %2, %0;" : "+l"(d) : "l"(a), "l"(b))

__device__ __forceinline__ float f2lo(unsigned long long v) { return __uint_as_float((unsigned)v); }
__device__ __forceinline__ float f2hi(unsigned long long v) { return __uint_as_float((unsigned)(v >> 32)); }

__device__ __forceinline__ float sigmoidf_(float x) { return 1.0f / (1.0f + __expf(-x)); }

// software grid barrier (all NC CTAs co-resident: grid <= SM count, 1 CTA/SM)
__device__ __forceinline__ void grid_sync() {
    __syncthreads();
    if (threadIdx.x == 0) {
        __threadfence();
        unsigned int old = atomicAdd(&g_bar, 1u);
        unsigned int target = (old / NC + 1u) * NC;
        unsigned int v;
        do {
            asm volatile("ld.acquire.gpu.global.u32 %0, [%1];"
                         : "=r"(v) : "l"(&g_bar) : "memory");
        } while (v < target);
    }
    __syncthreads();
}

// ---------------- init: h0 (B,H) -> transposed g_hT ----------------
__global__ void init_h_kernel(const float* __restrict__ h0) {
    int i = blockIdx.x * 256 + threadIdx.x;          // 131072 total
    int b = i >> 10;
    int k = i & (Hdim - 1);
    g_hT[k * Bsz + b] = h0[i];
}

// ---------------- phase A: x(65536x512) @ [Wiu|Wir|Wih](512x3072) + bias ----------------
__global__ void __launch_bounds__(256, 2) proj_kernel(
    const float* __restrict__ x,
    const float* __restrict__ Wiu, const float* __restrict__ Wir, const float* __restrict__ Wih,
    const float* __restrict__ bu,  const float* __restrict__ br,  const float* __restrict__ bh)
{
    __shared__ float  As[2][8][128];      // As[buf][k][m]
    __shared__ float2 Bs[2][8][128];      // Bs[buf][k][n]  duplicated lanes (w,w)

    const int tid = threadIdx.x;
    const int rb  = blockIdx.x * 128;     // row block in 65536
    const int cb  = blockIdx.y * 128;     // col block in 3072 (tiles never straddle gates)
    const int gate = cb >> 10;
    const int hc0  = cb & (Hdim - 1);
    const float* W    = (gate == 0) ? Wiu : (gate == 1 ? Wir : Wih);
    const float* bias = (gate == 0) ? bu  : (gate == 1 ? br  : bh);

    const int arow = tid >> 1;
    const int akk  = (tid & 1) * 4;
    const int bkr  = tid >> 5;
    const int bnc  = (tid & 31) * 4;
    const int tx = tid & 15, ty = tid >> 4;

    unsigned long long acc[4][8];
#pragma unroll
    for (int i = 0; i < 4; i++)
#pragma unroll
        for (int j = 0; j < 8; j++) acc[i][j] = 0ULL;

    {
        float4 a = *(const float4*)&x[(size_t)(rb + arow) * Din + akk];
        float4 w = *(const float4*)&W[(size_t)bkr * Hdim + hc0 + bnc];
        As[0][akk + 0][arow] = a.x; As[0][akk + 1][arow] = a.y;
        As[0][akk + 2][arow] = a.z; As[0][akk + 3][arow] = a.w;
        *(float4*)&Bs[0][bkr][bnc + 0] = make_float4(w.x, w.x, w.y, w.y);
        *(float4*)&Bs[0][bkr][bnc + 2] = make_float4(w.z, w.z, w.w, w.w);
    }
    __syncthreads();

    const int nsteps = Din / 8;   // 64
    for (int ks = 0; ks < nsteps; ks++) {
        const int cur = ks & 1;
        float4 pa, pw;
        const bool has = (ks + 1 < nsteps);
        if (has) {
            pa = *(const float4*)&x[(size_t)(rb + arow) * Din + (ks + 1) * 8 + akk];
            pw = *(const float4*)&W[(size_t)((ks + 1) * 8 + bkr) * Hdim + hc0 + bnc];
        }
#pragma unroll
        for (int kk = 0; kk < 8; kk++) {
            ulonglong2 a0 = *(const ulonglong2*)&As[cur][kk][ty * 8];
            ulonglong2 a1 = *(const ulonglong2*)&As[cur][kk][ty * 8 + 4];
            unsigned long long av[4] = { a0.x, a0.y, a1.x, a1.y };
            ulonglong2 b0 = *(const ulonglong2*)&Bs[cur][kk][tx * 8 + 0];
            ulonglong2 b1 = *(const ulonglong2*)&Bs[cur][kk][tx * 8 + 2];
            ulonglong2 b2 = *(const ulonglong2*)&Bs[cur][kk][tx * 8 + 4];
            ulonglong2 b3 = *(const ulonglong2*)&Bs[cur][kk][tx * 8 + 6];
            unsigned long long bv[8] = { b0.x, b0.y, b1.x, b1.y, b2.x, b2.y, b3.x, b3.y };
#pragma unroll
            for (int i = 0; i < 4; i++)
#pragma unroll
                for (int j = 0; j < 8; j++)
                    FMA2(acc[i][j], av[i], bv[j]);
        }
        if (has) {
            const int nxt = cur ^ 1;
            As[nxt][akk + 0][arow] = pa.x; As[nxt][akk + 1][arow] = pa.y;
            As[nxt][akk + 2][arow] = pa.z; As[nxt][akk + 3][arow] = pa.w;
            *(float4*)&Bs[nxt][bkr][bnc + 0] = make_float4(pw.x, pw.x, pw.y, pw.y);
            *(float4*)&Bs[nxt][bkr][bnc + 2] = make_float4(pw.z, pw.z, pw.w, pw.w);
        }
        __syncthreads();
    }

    float bias8[8];
#pragma unroll
    for (int j = 0; j < 8; j++) bias8[j] = bias[hc0 + tx * 8 + j];

    float* gout = g_xproj + (size_t)gate * TBH;
#pragma unroll
    for (int i = 0; i < 4; i++) {
#pragma unroll
        for (int half = 0; half < 2; half++) {
            const int r  = rb + ty * 8 + i * 2 + half;
            const int t  = r & (Tseq - 1);
            const int bb = r >> 9;
            float* dst = gout + ((size_t)(t * Bsz + bb)) * Hdim + hc0 + tx * 8;
            float v[8];
#pragma unroll
            for (int j = 0; j < 8; j++)
                v[j] = (half ? f2hi(acc[i][j]) : f2lo(acc[i][j])) + bias8[j];
            *(float4*)&dst[0] = make_float4(v[0], v[1], v[2], v[3]);
            *(float4*)&dst[4] = make_float4(v[4], v[5], v[6], v[7]);
        }
    }
}

// ---------------- persistent recurrence: all 512 steps in ONE kernel ----------------
// grid = 128 CTAs x 256 threads. Per step:
//   phase1: z (CTAs 0..63) / r (CTAs 64..127), 16 cols each of Whu/Whr. grid_sync.
//   phase2: candidate + gated update, 8 cols of Whh per CTA (k split across warp halves). grid_sync.
__global__ void __launch_bounds__(256) gru_rec_kernel(
    const float* __restrict__ Whu, const float* __restrict__ Whr,
    const float* __restrict__ Whh, float* __restrict__ out)
{
    __shared__ float  sh[64][128];     // A tile (h or r*h), 32 KB
    __shared__ float2 sw[64][16];      // weight tile, duplicated (w,w), 16 KB
    __shared__ float  sp[8][128];      // phase2 partial sums, 4 KB

    const int tid  = threadIdx.x;
    const int cta  = blockIdx.x;
    const int wid  = tid >> 5, lane = tid & 31;
    const int bg   = lane & 7, ng = lane >> 3;

    // phase1 mapping: 8 warps = 4 b-rows x 2 n-cols(8); thread = 4b x 2n
    const int b0   = (wid & 3) * 32 + bg * 4;
    const int p1n  = (wid >> 2) * 8 + ng * 2;
    const int isR  = cta >= 64;
    const float* __restrict__ Wzr = isR ? Whr : Whu;
    const int cb1  = (isR ? cta - 64 : cta) * 16;

    // phase2 mapping: 8 warps = 4 b-rows x 2 k-halves; thread = 4b x 2n (8 cols total)
    const int b02  = (wid & 3) * 32 + bg * 4;
    const int wk2  = wid >> 2;
    const int nl2  = ng * 2;
    const int cb2  = cta * 8;

    // fill loader indices
    const int wl_kk1 = tid >> 2, wl_j1 = (tid & 3) * 4;   // phase1 weight fill
    const int wl_kk2 = tid >> 1, wl_j2 = (tid & 1) * 4;   // phase2 weight fill (tid<128)

    for (int t = 0; t < Tseq; t++) {
        // ================= phase 1: z / r gates =================
        unsigned long long a00 = 0, a01 = 0, a10 = 0, a11 = 0;
        for (int k0 = 0; k0 < Hdim; k0 += 64) {
            const float4* hsrc = (const float4*)(g_hT + (size_t)k0 * Bsz);
#pragma unroll
            for (int p = 0; p < 8; p++)
                ((float4*)sh)[p * 256 + tid] = hsrc[p * 256 + tid];
            {
                float4 w = *(const float4*)&Wzr[(size_t)(k0 + wl_kk1) * Hdim + cb1 + wl_j1];
                sw[wl_kk1][wl_j1 + 0] = make_float2(w.x, w.x);
                sw[wl_kk1][wl_j1 + 1] = make_float2(w.y, w.y);
                sw[wl_kk1][wl_j1 + 2] = make_float2(w.z, w.z);
                sw[wl_kk1][wl_j1 + 3] = make_float2(w.w, w.w);
            }
            __syncthreads();
#pragma unroll 8
            for (int kk = 0; kk < 64; kk++) {
                ulonglong2 hv = *(const ulonglong2*)&sh[kk][b0];
                ulonglong2 wv = *(const ulonglong2*)&sw[kk][p1n];
                FMA2(a00, hv.x, wv.x); FMA2(a10, hv.y, wv.x);
                FMA2(a01, hv.x, wv.y); FMA2(a11, hv.y, wv.y);
            }
            __syncthreads();
        }
        {
            const float* xg = g_xproj + (isR ? TBH : 0) + (size_t)t * BH;
#pragma unroll
            for (int j = 0; j < 2; j++) {
                const int nn = cb1 + p1n + j;
                unsigned long long pA = j ? a01 : a00;
                unsigned long long pB = j ? a11 : a10;
                float s0 = sigmoidf_(f2lo(pA) + xg[(size_t)(b0 + 0) * Hdim + nn]);
                float s1 = sigmoidf_(f2hi(pA) + xg[(size_t)(b0 + 1) * Hdim + nn]);
                float s2 = sigmoidf_(f2lo(pB) + xg[(size_t)(b0 + 2) * Hdim + nn]);
                float s3 = sigmoidf_(f2hi(pB) + xg[(size_t)(b0 + 3) * Hdim + nn]);
                if (!isR) {
                    *(float4*)&g_zT[nn * Bsz + b0] = make_float4(s0, s1, s2, s3);
                } else {
                    float4 h4 = *(const float4*)&g_hT[nn * Bsz + b0];
                    *(float4*)&g_rhT[nn * Bsz + b0] =
                        make_float4(s0 * h4.x, s1 * h4.y, s2 * h4.z, s3 * h4.w);
                }
            }
        }
        grid_sync();

        // ================= phase 2: candidate + update =================
        unsigned long long c00 = 0, c01 = 0, c10 = 0, c11 = 0;
        for (int k0 = 0; k0 < Hdim; k0 += 64) {
            const float4* asrc = (const float4*)(g_rhT + (size_t)k0 * Bsz);
#pragma unroll
            for (int p = 0; p < 8; p++)
                ((float4*)sh)[p * 256 + tid] = asrc[p * 256 + tid];
            if (tid < 128) {
                float4 w = *(const float4*)&Whh[(size_t)(k0 + wl_kk2) * Hdim + cb2 + wl_j2];
                sw[wl_kk2][wl_j2 + 0] = make_float2(w.x, w.x);
                sw[wl_kk2][wl_j2 + 1] = make_float2(w.y, w.y);
                sw[wl_kk2][wl_j2 + 2] = make_float2(w.z, w.z);
                sw[wl_kk2][wl_j2 + 3] = make_float2(w.w, w.w);
            }
            __syncthreads();
            const int kbeg = wk2 * 32;
#pragma unroll 8
            for (int kk = kbeg; kk < kbeg + 32; kk++) {
                ulonglong2 hv = *(const ulonglong2*)&sh[kk][b02];
                ulonglong2 wv = *(const ulonglong2*)&sw[kk][nl2];
                FMA2(c00, hv.x, wv.x); FMA2(c10, hv.y, wv.x);
                FMA2(c01, hv.x, wv.y); FMA2(c11, hv.y, wv.y);
            }
            __syncthreads();
        }
        if (wk2 == 1) {
            *(float4*)&sp[nl2 + 0][b02] = make_float4(f2lo(c00), f2hi(c00), f2lo(c10), f2hi(c10));
            *(float4*)&sp[nl2 + 1][b02] = make_float4(f2lo(c01), f2hi(c01), f2lo(c11), f2hi(c11));
        }
        __syncthreads();
        if (wk2 == 0) {
            const float* xh = g_xproj + 2 * TBH + (size_t)t * BH;
#pragma unroll
            for (int j = 0; j < 2; j++) {
                const int nn = cb2 + nl2 + j;
                unsigned long long pA = j ? c01 : c00;
                unsigned long long pB = j ? c11 : c10;
                float4 part = *(const float4*)&sp[nl2 + j][b02];
                float d0 = f2lo(pA) + part.x + xh[(size_t)(b02 + 0) * Hdim + nn];
                float d1 = f2hi(pA) + part.y + xh[(size_t)(b02 + 1) * Hdim + nn];
                float d2 = f2lo(pB) + part.z + xh[(size_t)(b02 + 2) * Hdim + nn];
                float d3 = f2hi(pB) + part.w + xh[(size_t)(b02 + 3) * Hdim + nn];
                float4 z4 = *(const float4*)&g_zT[nn * Bsz + b02];
                float4 h4 = *(const float4*)&g_hT[nn * Bsz + b02];
                float hn0 = h4.x + z4.x * (tanhf(d0) - h4.x);
                float hn1 = h4.y + z4.y * (tanhf(d1) - h4.y);
                float hn2 = h4.z + z4.z * (tanhf(d2) - h4.z);
                float hn3 = h4.w + z4.w * (tanhf(d3) - h4.w);
                *(float4*)&g_hT[nn * Bsz + b02] = make_float4(hn0, hn1, hn2, hn3);
                if (out) {
                    float* ob = out + (size_t)t * BH + nn;
                    ob[(size_t)(b02 + 0) * Hdim] = hn0;
                    ob[(size_t)(b02 + 1) * Hdim] = hn1;
                    ob[(size_t)(b02 + 2) * Hdim] = hn2;
                    ob[(size_t)(b02 + 3) * Hdim] = hn3;
                }
            }
        }
        grid_sync();
    }
}

// ---------------- final hidden state: transpose g_hT -> (B,H) ----------------
__global__ void hlast_kernel(float* __restrict__ dst) {
    int i = blockIdx.x * 256 + threadIdx.x;       // 131072
    int b = i >> 10;
    int k = i & (Hdim - 1);
    dst[i] = g_hT[k * Bsz + b];
}

// ---------------- launch ----------------
extern "C" void kernel_launch(void* const* d_in, const int* in_sizes, int n_in,
                              void* d_out, int out_size)
{
    (void)in_sizes; (void)n_in;
    const float* x   = (const float*)d_in[0];
    const float* h0  = (const float*)d_in[1];
    const float* Wiu = (const float*)d_in[2];
    const float* Whu = (const float*)d_in[3];
    const float* bu  = (const float*)d_in[4];
    const float* Wir = (const float*)d_in[5];
    const float* Whr = (const float*)d_in[6];
    const float* br  = (const float*)d_in[7];
    const float* Wih = (const float*)d_in[8];
    const float* Whh = (const float*)d_in[9];
    const float* bh  = (const float*)d_in[10];
    float* out = (float*)d_out;

    const bool write_seq  = ((size_t)out_size >= TBH);
    const bool write_last = ((size_t)out_size >= TBH + (size_t)Bsz * Hdim);

    init_h_kernel<<<512, 256>>>(h0);

    dim3 pg(65536 / 128, 3072 / 128);   // 512 x 24
    proj_kernel<<<pg, 256>>>(x, Wiu, Wir, Wih, bu, br, bh);

    gru_rec_kernel<<<NC, 256>>>(Whu, Whr, Whh, write_seq ? out : nullptr);

    if (write_last)        hlast_kernel<<<512, 256>>>(out + TBH);
    else if (!write_seq)   hlast_kernel<<<512, 256>>>(out);   // output is h_last only
}

// round 3
// speedup vs baseline: 1.5002x; 1.5002x over previous
#include <cuda_runtime.h>
#include <cstdint>

#define Bsz  128
#define Tseq 512
#define Din  512
#define Hdim 1024
#define BH   (Bsz * Hdim)
#define TBH  ((size_t)Tseq * (size_t)Bsz * (size_t)Hdim)
#define NC   128     // persistent CTAs
#define NT   128     // threads per CTA (recurrence)
#define KC   128     // k-chunk

// ---------------- static device scratch ----------------
__device__ float g_xproj[3ULL * 512ULL * 128ULL * 1024ULL]; // (gate, t, b, h)
__device__ float g_hT [Hdim * Bsz];   // h transposed [k][b]
__device__ float g_zT [Hdim * Bsz];
__device__ float g_rhT[Hdim * Bsz];
__device__ unsigned int g_bar = 0;

#define FMA2(d, a, b) asm("fma.rn.f32x2 %0, %1, %2, %0;" : "+l"(d) : "l"(a), "l"(b))
__device__ __forceinline__ float f2lo(unsigned long long v) { return __uint_as_float((unsigned)v); }
__device__ __forceinline__ float f2hi(unsigned long long v) { return __uint_as_float((unsigned)(v >> 32)); }
__device__ __forceinline__ unsigned long long dup2(float w) {
    unsigned long long r; asm("mov.b64 %0, {%1, %1};" : "=l"(r) : "f"(w)); return r;
}
__device__ __forceinline__ float sigmoidf_(float x) { return 1.0f / (1.0f + __expf(-x)); }

__device__ __forceinline__ void cp16(void* s, const void* g) {
    unsigned sa = (unsigned)__cvta_generic_to_shared(s);
    asm volatile("cp.async.ca.shared.global [%0], [%1], 16;" :: "r"(sa), "l"(g));
}
#define CP_COMMIT() asm volatile("cp.async.commit_group;")
#define CP_WAIT1()  asm volatile("cp.async.wait_group 1;")
#define CP_WAIT0()  asm volatile("cp.async.wait_group 0;")

__device__ __forceinline__ void grid_sync() {
    __syncthreads();
    if (threadIdx.x == 0) {
        __threadfence();
        unsigned int old = atomicAdd(&g_bar, 1u);
        unsigned int target = (old / NC + 1u) * NC;
        unsigned int v;
        do {
            asm volatile("ld.acquire.gpu.global.u32 %0, [%1];"
                         : "=r"(v) : "l"(&g_bar) : "memory");
        } while (v < target);
    }
    __syncthreads();
}

// ---------------- init: h0 (B,H) -> transposed g_hT ----------------
__global__ void init_h_kernel(const float* __restrict__ h0) {
    int i = blockIdx.x * 256 + threadIdx.x;
    int b = i >> 10;
    int k = i & (Hdim - 1);
    g_hT[k * Bsz + b] = h0[i];
}

// ---------------- phase A: x @ [Wiu|Wir|Wih] + bias (unchanged from R2) ----------------
__global__ void __launch_bounds__(256, 2) proj_kernel(
    const float* __restrict__ x,
    const float* __restrict__ Wiu, const float* __restrict__ Wir, const float* __restrict__ Wih,
    const float* __restrict__ bu,  const float* __restrict__ br,  const float* __restrict__ bh)
{
    __shared__ float  As[2][8][128];
    __shared__ float2 Bs[2][8][128];

    const int tid = threadIdx.x;
    const int rb  = blockIdx.x * 128;
    const int cb  = blockIdx.y * 128;
    const int gate = cb >> 10;
    const int hc0  = cb & (Hdim - 1);
    const float* W    = (gate == 0) ? Wiu : (gate == 1 ? Wir : Wih);
    const float* bias = (gate == 0) ? bu  : (gate == 1 ? br  : bh);

    const int arow = tid >> 1;
    const int akk  = (tid & 1) * 4;
    const int bkr  = tid >> 5;
    const int bnc  = (tid & 31) * 4;
    const int tx = tid & 15, ty = tid >> 4;

    unsigned long long acc[4][8];
#pragma unroll
    for (int i = 0; i < 4; i++)
#pragma unroll
        for (int j = 0; j < 8; j++) acc[i][j] = 0ULL;

    {
        float4 a = *(const float4*)&x[(size_t)(rb + arow) * Din + akk];
        float4 w = *(const float4*)&W[(size_t)bkr * Hdim + hc0 + bnc];
        As[0][akk + 0][arow] = a.x; As[0][akk + 1][arow] = a.y;
        As[0][akk + 2][arow] = a.z; As[0][akk + 3][arow] = a.w;
        *(float4*)&Bs[0][bkr][bnc + 0] = make_float4(w.x, w.x, w.y, w.y);
        *(float4*)&Bs[0][bkr][bnc + 2] = make_float4(w.z, w.z, w.w, w.w);
    }
    __syncthreads();

    const int nsteps = Din / 8;
    for (int ks = 0; ks < nsteps; ks++) {
        const int cur = ks & 1;
        float4 pa, pw;
        const bool has = (ks + 1 < nsteps);
        if (has) {
            pa = *(const float4*)&x[(size_t)(rb + arow) * Din + (ks + 1) * 8 + akk];
            pw = *(const float4*)&W[(size_t)((ks + 1) * 8 + bkr) * Hdim + hc0 + bnc];
        }
#pragma unroll
        for (int kk = 0; kk < 8; kk++) {
            ulonglong2 a0 = *(const ulonglong2*)&As[cur][kk][ty * 8];
            ulonglong2 a1 = *(const ulonglong2*)&As[cur][kk][ty * 8 + 4];
            unsigned long long av[4] = { a0.x, a0.y, a1.x, a1.y };
            ulonglong2 b0 = *(const ulonglong2*)&Bs[cur][kk][tx * 8 + 0];
            ulonglong2 b1 = *(const ulonglong2*)&Bs[cur][kk][tx * 8 + 2];
            ulonglong2 b2 = *(const ulonglong2*)&Bs[cur][kk][tx * 8 + 4];
            ulonglong2 b3 = *(const ulonglong2*)&Bs[cur][kk][tx * 8 + 6];
            unsigned long long bv[8] = { b0.x, b0.y, b1.x, b1.y, b2.x, b2.y, b3.x, b3.y };
#pragma unroll
            for (int i = 0; i < 4; i++)
#pragma unroll
                for (int j = 0; j < 8; j++)
                    FMA2(acc[i][j], av[i], bv[j]);
        }
        if (has) {
            const int nxt = cur ^ 1;
            As[nxt][akk + 0][arow] = pa.x; As[nxt][akk + 1][arow] = pa.y;
            As[nxt][akk + 2][arow] = pa.z; As[nxt][akk + 3][arow] = pa.w;
            *(float4*)&Bs[nxt][bkr][bnc + 0] = make_float4(pw.x, pw.x, pw.y, pw.y);
            *(float4*)&Bs[nxt][bkr][bnc + 2] = make_float4(pw.z, pw.z, pw.w, pw.w);
        }
        __syncthreads();
    }

    float bias8[8];
#pragma unroll
    for (int j = 0; j < 8; j++) bias8[j] = bias[hc0 + tx * 8 + j];

    float* gout = g_xproj + (size_t)gate * TBH;
#pragma unroll
    for (int i = 0; i < 4; i++) {
#pragma unroll
        for (int half = 0; half < 2; half++) {
            const int r  = rb + ty * 8 + i * 2 + half;
            const int t  = r & (Tseq - 1);
            const int bb = r >> 9;
            float* dst = gout + ((size_t)(t * Bsz + bb)) * Hdim + hc0 + tx * 8;
            float v[8];
#pragma unroll
            for (int j = 0; j < 8; j++)
                v[j] = (half ? f2hi(acc[i][j]) : f2lo(acc[i][j])) + bias8[j];
            *(float4*)&dst[0] = make_float4(v[0], v[1], v[2], v[3]);
            *(float4*)&dst[4] = make_float4(v[4], v[5], v[6], v[7]);
        }
    }
}

// ---------------- persistent recurrence ----------------
// dynamic smem layout (bytes):
//   [0,      32768)  weight double-buffer (phase1: 2 x KC x 32 f; phase2 uses 2 x KC x 16 f)
//   [32768,  98304)  h/rh tile double-buffer: 2 x KC x 64 floats
//   [98304, 131072)  partial sums: u64[4][32][32] (phase1) / u64[4][16][32] (phase2)
#define SMEM_BYTES 131072

__global__ void __launch_bounds__(NT, 1) gru_rec_kernel(
    const float* __restrict__ Whu, const float* __restrict__ Whr,
    const float* __restrict__ Whh, float* __restrict__ out)
{
    extern __shared__ char smem_raw[];
    float* SW = (float*)smem_raw;                       // weights
    float* SH = (float*)(smem_raw + 32768);             // h tiles
    unsigned long long* PART = (unsigned long long*)(smem_raw + 98304);

    const int tid  = threadIdx.x;
    const int cta  = blockIdx.x;
    const int ws   = tid >> 5;            // warp = k-slice (0..3)
    const int lane = tid & 31;
    const int bpos = lane & 7;            // 8 b-groups of 8
    const int npos = lane >> 3;           // 4 n-groups

    const int bhalf = cta & 1;            // which 64-row half of b
    const int ngrp  = cta >> 1;           // 0..63

    // phase1: z (ngrp 0..31) or r (ngrp 32..63), 32 cols
    const int isR  = ngrp >= 32;
    const float* __restrict__ Wzr = isR ? Whr : Whu;
    const int col1 = (isR ? ngrp - 32 : ngrp) * 32;     // H-col base (also output n base)
    // phase2: 16 cols of Whh
    const int n2 = ngrp * 16;

    const int bbase = bhalf * 64;

    for (int t = 0; t < Tseq; t++) {
        // ======================= phase 1 : z / r =======================
        unsigned long long acc[8][4];
#pragma unroll
        for (int j = 0; j < 8; j++)
#pragma unroll
            for (int i = 0; i < 4; i++) acc[j][i] = 0ULL;

        // prologue: chunk 0
        {
#pragma unroll
            for (int q = 0; q < 16; q++) {              // h: KC x 64 f = 2048 f4
                int idx = tid + q * NT;
                int row = idx >> 4, c4 = (idx & 15) * 4;
                cp16(SH + (size_t)row * 64 + c4, g_hT + (size_t)row * Bsz + bbase + c4);
            }
#pragma unroll
            for (int q = 0; q < 8; q++) {               // w: KC x 32 f = 1024 f4
                int idx = tid + q * NT;
                int row = idx >> 3, c4 = (idx & 7) * 4;
                cp16(SW + (size_t)row * 32 + c4, Wzr + (size_t)row * Hdim + col1 + c4);
            }
            CP_COMMIT();
        }

        int buf = 0;
        for (int cc = 0; cc < 8; cc++) {
            if (cc < 7) {
                const int k0 = (cc + 1) * KC;
                const int ob = buf ^ 1;
#pragma unroll
                for (int q = 0; q < 16; q++) {
                    int idx = tid + q * NT;
                    int row = idx >> 4, c4 = (idx & 15) * 4;
                    cp16(SH + (size_t)(ob * KC + row) * 64 + c4,
                         g_hT + (size_t)(k0 + row) * Bsz + bbase + c4);
                }
#pragma unroll
                for (int q = 0; q < 8; q++) {
                    int idx = tid + q * NT;
                    int row = idx >> 3, c4 = (idx & 7) * 4;
                    cp16(SW + (size_t)(ob * KC + row) * 32 + c4,
                         Wzr + (size_t)(k0 + row) * Hdim + col1 + c4);
                }
                CP_COMMIT();
                CP_WAIT1();
            } else {
                CP_WAIT0();
            }
            __syncthreads();

            const float* hb = SH + (size_t)buf * KC * 64;
            const float* wb = SW + (size_t)buf * KC * 32;
#pragma unroll 8
            for (int kk = 0; kk < 32; kk++) {
                const int kr = ws * 32 + kk;
                const float* hr = hb + kr * 64 + bpos * 8;
                ulonglong2 hA = *(const ulonglong2*)(hr);
                ulonglong2 hB = *(const ulonglong2*)(hr + 4);
                const float* wr = wb + kr * 32 + npos * 8;
                float4 wA = *(const float4*)(wr);
                float4 wB = *(const float4*)(wr + 4);
                unsigned long long wd[8] = {
                    dup2(wA.x), dup2(wA.y), dup2(wA.z), dup2(wA.w),
                    dup2(wB.x), dup2(wB.y), dup2(wB.z), dup2(wB.w) };
#pragma unroll
                for (int j = 0; j < 8; j++) {
                    FMA2(acc[j][0], hA.x, wd[j]);
                    FMA2(acc[j][1], hA.y, wd[j]);
                    FMA2(acc[j][2], hB.x, wd[j]);
                    FMA2(acc[j][3], hB.y, wd[j]);
                }
            }
            __syncthreads();
            buf ^= 1;
        }

        // partials: PART[ws][n_local(32)][bpair(32)]
#pragma unroll
        for (int j = 0; j < 8; j++)
#pragma unroll
            for (int i = 0; i < 4; i++)
                PART[((size_t)ws * 32 + npos * 8 + j) * 32 + bpos * 4 + i] = acc[j][i];
        __syncthreads();

        // epilogue: thread -> n = tid>>2 (32), local-b run = (tid&3)*16
        {
            const int nl = tid >> 2;
            const int bl = (tid & 3) * 16;
            float s[16];
#pragma unroll
            for (int q = 0; q < 8; q++) {
                float sx = 0.f, sy = 0.f;
#pragma unroll
                for (int w = 0; w < 4; w++) {
                    unsigned long long p = PART[((size_t)w * 32 + nl) * 32 + (bl >> 1) + q];
                    sx += f2lo(p); sy += f2hi(p);
                }
                s[2 * q] = sx; s[2 * q + 1] = sy;
            }
            const int n = col1 + nl;
            const int b = bbase + bl;
            const float* xg = g_xproj + (isR ? TBH : 0) + (size_t)t * BH;
#pragma unroll
            for (int i = 0; i < 16; i++)
                s[i] = sigmoidf_(s[i] + xg[(size_t)(b + i) * Hdim + n]);
            if (!isR) {
#pragma unroll
                for (int v = 0; v < 4; v++)
                    *(float4*)&g_zT[n * Bsz + b + v * 4] =
                        make_float4(s[4*v], s[4*v+1], s[4*v+2], s[4*v+3]);
            } else {
#pragma unroll
                for (int v = 0; v < 4; v++) {
                    float4 h4 = *(const float4*)&g_hT[n * Bsz + b + v * 4];
                    *(float4*)&g_rhT[n * Bsz + b + v * 4] =
                        make_float4(s[4*v]*h4.x, s[4*v+1]*h4.y, s[4*v+2]*h4.z, s[4*v+3]*h4.w);
                }
            }
        }
        grid_sync();

        // ======================= phase 2 : candidate + update =======================
        unsigned long long ac2[4][4];
#pragma unroll
        for (int j = 0; j < 4; j++)
#pragma unroll
            for (int i = 0; i < 4; i++) ac2[j][i] = 0ULL;

        {
#pragma unroll
            for (int q = 0; q < 16; q++) {
                int idx = tid + q * NT;
                int row = idx >> 4, c4 = (idx & 15) * 4;
                cp16(SH + (size_t)row * 64 + c4, g_rhT + (size_t)row * Bsz + bbase + c4);
            }
#pragma unroll
            for (int q = 0; q < 4; q++) {               // w2: KC x 16 f = 512 f4
                int idx = tid + q * NT;
                int row = idx >> 2, c4 = (idx & 3) * 4;
                cp16(SW + (size_t)row * 16 + c4, Whh + (size_t)row * Hdim + n2 + c4);
            }
            CP_COMMIT();
        }

        buf = 0;
        for (int cc = 0; cc < 8; cc++) {
            if (cc < 7) {
                const int k0 = (cc + 1) * KC;
                const int ob = buf ^ 1;
#pragma unroll
                for (int q = 0; q < 16; q++) {
                    int idx = tid + q * NT;
                    int row = idx >> 4, c4 = (idx & 15) * 4;
                    cp16(SH + (size_t)(ob * KC + row) * 64 + c4,
                         g_rhT + (size_t)(k0 + row) * Bsz + bbase + c4);
                }
#pragma unroll
                for (int q = 0; q < 4; q++) {
                    int idx = tid + q * NT;
                    int row = idx >> 2, c4 = (idx & 3) * 4;
                    cp16(SW + (size_t)(ob * KC + row) * 16 + c4,
                         Whh + (size_t)(k0 + row) * Hdim + n2 + c4);
                }
                CP_COMMIT();
                CP_WAIT1();
            } else {
                CP_WAIT0();
            }
            __syncthreads();

            const float* hb = SH + (size_t)buf * KC * 64;
            const float* wb = SW + (size_t)buf * KC * 16;
#pragma unroll 8
            for (int kk = 0; kk < 32; kk++) {
                const int kr = ws * 32 + kk;
                const float* hr = hb + kr * 64 + bpos * 8;
                ulonglong2 hA = *(const ulonglong2*)(hr);
                ulonglong2 hB = *(const ulonglong2*)(hr + 4);
                float4 w4 = *(const float4*)(wb + kr * 16 + npos * 4);
                unsigned long long wd[4] = { dup2(w4.x), dup2(w4.y), dup2(w4.z), dup2(w4.w) };
#pragma unroll
                for (int j = 0; j < 4; j++) {
                    FMA2(ac2[j][0], hA.x, wd[j]);
                    FMA2(ac2[j][1], hA.y, wd[j]);
                    FMA2(ac2[j][2], hB.x, wd[j]);
                    FMA2(ac2[j][3], hB.y, wd[j]);
                }
            }
            __syncthreads();
            buf ^= 1;
        }

        // partials: PART[ws][n_local(16)][bpair(32)]
#pragma unroll
        for (int j = 0; j < 4; j++)
#pragma unroll
            for (int i = 0; i < 4; i++)
                PART[((size_t)ws * 16 + npos * 4 + j) * 32 + bpos * 4 + i] = ac2[j][i];
        __syncthreads();

        // epilogue: thread -> n_local = tid&15, b run = (tid>>4)*8
        {
            const int nl = tid & 15;
            const int bl = (tid >> 4) * 8;
            float s[8];
#pragma unroll
            for (int q = 0; q < 4; q++) {
                float sx = 0.f, sy = 0.f;
#pragma unroll
                for (int w = 0; w < 4; w++) {
                    unsigned long long p = PART[((size_t)w * 16 + nl) * 32 + (bl >> 1) + q];
                    sx += f2lo(p); sy += f2hi(p);
                }
                s[2 * q] = sx; s[2 * q + 1] = sy;
            }
            const int n = n2 + nl;
            const int b = bbase + bl;
            const float* xh = g_xproj + 2 * TBH + (size_t)t * BH;
            float hn[8];
#pragma unroll
            for (int v = 0; v < 2; v++) {
                float4 z4 = *(const float4*)&g_zT[n * Bsz + b + v * 4];
                float4 h4 = *(const float4*)&g_hT[n * Bsz + b + v * 4];
                float zz[4] = { z4.x, z4.y, z4.z, z4.w };
                float hh[4] = { h4.x, h4.y, h4.z, h4.w };
#pragma unroll
                for (int i = 0; i < 4; i++) {
                    int e = v * 4 + i;
                    float c = tanhf(s[e] + xh[(size_t)(b + e) * Hdim + n]);
                    hn[e] = hh[i] + zz[i] * (c - hh[i]);
                }
                *(float4*)&g_hT[n * Bsz + b + v * 4] =
                    make_float4(hn[v*4], hn[v*4+1], hn[v*4+2], hn[v*4+3]);
            }
            if (out) {
                float* ob = out + (size_t)t * BH + n;
#pragma unroll
                for (int e = 0; e < 8; e++)
                    ob[(size_t)(b + e) * Hdim] = hn[e];
            }
        }
        grid_sync();
    }
}

// ---------------- final hidden state ----------------
__global__ void hlast_kernel(float* __restrict__ dst) {
    int i = blockIdx.x * 256 + threadIdx.x;
    int b = i >> 10;
    int k = i & (Hdim - 1);
    dst[i] = g_hT[k * Bsz + b];
}

// ---------------- launch ----------------
extern "C" void kernel_launch(void* const* d_in, const int* in_sizes, int n_in,
                              void* d_out, int out_size)
{
    (void)in_sizes; (void)n_in;
    const float* x   = (const float*)d_in[0];
    const float* h0  = (const float*)d_in[1];
    const float* Wiu = (const float*)d_in[2];
    const float* Whu = (const float*)d_in[3];
    const float* bu  = (const float*)d_in[4];
    const float* Wir = (const float*)d_in[5];
    const float* Whr = (const float*)d_in[6];
    const float* br  = (const float*)d_in[7];
    const float* Wih = (const float*)d_in[8];
    const float* Whh = (const float*)d_in[9];
    const float* bh  = (const float*)d_in[10];
    float* out = (float*)d_out;

    const bool write_seq  = ((size_t)out_size >= TBH);
    const bool write_last = ((size_t)out_size >= TBH + (size_t)Bsz * Hdim);

    cudaFuncSetAttribute(gru_rec_kernel,
                         cudaFuncAttributeMaxDynamicSharedMemorySize, SMEM_BYTES);

    init_h_kernel<<<512, 256>>>(h0);

    dim3 pg(65536 / 128, 3072 / 128);
    proj_kernel<<<pg, 256>>>(x, Wiu, Wir, Wih, bu, br, bh);

    gru_rec_kernel<<<NC, NT, SMEM_BYTES>>>(Whu, Whr, Whh, write_seq ? out : nullptr);

    if (write_last)        hlast_kernel<<<512, 256>>>(out + TBH);
    else if (!write_seq)   hlast_kernel<<<512, 256>>>(out);
}

// round 4
// speedup vs baseline: 1.7163x; 1.1440x over previous
#include <cuda_runtime.h>
#include <cstdint>

#define Bsz  128
#define Tseq 512
#define Din  512
#define Hdim 1024
#define BH   (Bsz * Hdim)
#define TBH  ((size_t)Tseq * (size_t)Bsz * (size_t)Hdim)
#define NC   128     // persistent CTAs
#define NT   256     // threads per CTA (recurrence): 8 warps = 2/SMSP
#define KC   128     // k-chunk

// ---------------- static device scratch ----------------
__device__ float g_xproj[3ULL * 512ULL * 128ULL * 1024ULL]; // (gate, t, b, h)
__device__ float g_hT [Hdim * Bsz];   // h transposed [k][b]
__device__ float g_zT [Hdim * Bsz];
__device__ float g_rhT[Hdim * Bsz];
__device__ unsigned int g_bar = 0;

#define FMA2(d, a, b) asm("fma.rn.f32x2 %0, %1, %2, %0;" : "+l"(d) : "l"(a), "l"(b))
__device__ __forceinline__ float f2lo(unsigned long long v) { return __uint_as_float((unsigned)v); }
__device__ __forceinline__ float f2hi(unsigned long long v) { return __uint_as_float((unsigned)(v >> 32)); }
__device__ __forceinline__ unsigned long long dup2(float w) {
    unsigned long long r; asm("mov.b64 %0, {%1, %1};" : "=l"(r) : "f"(w)); return r;
}
__device__ __forceinline__ float sigmoidf_(float x) { return 1.0f / (1.0f + __expf(-x)); }

__device__ __forceinline__ void cp16(void* s, const void* g) {
    unsigned sa = (unsigned)__cvta_generic_to_shared(s);
    asm volatile("cp.async.cg.shared.global [%0], [%1], 16;" :: "r"(sa), "l"(g));
}
#define CP_COMMIT() asm volatile("cp.async.commit_group;")
#define CP_WAIT1()  asm volatile("cp.async.wait_group 1;")
#define CP_WAIT0()  asm volatile("cp.async.wait_group 0;")

__device__ __forceinline__ void grid_sync() {
    __syncthreads();
    if (threadIdx.x == 0) {
        __threadfence();
        unsigned int old = atomicAdd(&g_bar, 1u);
        unsigned int target = (old / NC + 1u) * NC;
        unsigned int v;
        do {
            asm volatile("ld.acquire.gpu.global.u32 %0, [%1];"
                         : "=r"(v) : "l"(&g_bar) : "memory");
        } while (v < target);
    }
    __syncthreads();
}

// ---------------- init: h0 (B,H) -> transposed g_hT ----------------
__global__ void init_h_kernel(const float* __restrict__ h0) {
    int i = blockIdx.x * 256 + threadIdx.x;
    int b = i >> 10;
    int k = i & (Hdim - 1);
    g_hT[k * Bsz + b] = h0[i];
}

// ---------------- phase A: x @ [Wiu|Wir|Wih] + bias ----------------
__global__ void __launch_bounds__(256, 2) proj_kernel(
    const float* __restrict__ x,
    const float* __restrict__ Wiu, const float* __restrict__ Wir, const float* __restrict__ Wih,
    const float* __restrict__ bu,  const float* __restrict__ br,  const float* __restrict__ bh)
{
    __shared__ float  As[2][8][128];
    __shared__ float2 Bs[2][8][128];

    const int tid = threadIdx.x;
    const int rb  = blockIdx.x * 128;
    const int cb  = blockIdx.y * 128;
    const int gate = cb >> 10;
    const int hc0  = cb & (Hdim - 1);
    const float* W    = (gate == 0) ? Wiu : (gate == 1 ? Wir : Wih);
    const float* bias = (gate == 0) ? bu  : (gate == 1 ? br  : bh);

    const int arow = tid >> 1;
    const int akk  = (tid & 1) * 4;
    const int bkr  = tid >> 5;
    const int bnc  = (tid & 31) * 4;
    const int tx = tid & 15, ty = tid >> 4;

    unsigned long long acc[4][8];
#pragma unroll
    for (int i = 0; i < 4; i++)
#pragma unroll
        for (int j = 0; j < 8; j++) acc[i][j] = 0ULL;

    {
        float4 a = *(const float4*)&x[(size_t)(rb + arow) * Din + akk];
        float4 w = *(const float4*)&W[(size_t)bkr * Hdim + hc0 + bnc];
        As[0][akk + 0][arow] = a.x; As[0][akk + 1][arow] = a.y;
        As[0][akk + 2][arow] = a.z; As[0][akk + 3][arow] = a.w;
        *(float4*)&Bs[0][bkr][bnc + 0] = make_float4(w.x, w.x, w.y, w.y);
        *(float4*)&Bs[0][bkr][bnc + 2] = make_float4(w.z, w.z, w.w, w.w);
    }
    __syncthreads();

    const int nsteps = Din / 8;
    for (int ks = 0; ks < nsteps; ks++) {
        const int cur = ks & 1;
        float4 pa, pw;
        const bool has = (ks + 1 < nsteps);
        if (has) {
            pa = *(const float4*)&x[(size_t)(rb + arow) * Din + (ks + 1) * 8 + akk];
            pw = *(const float4*)&W[(size_t)((ks + 1) * 8 + bkr) * Hdim + hc0 + bnc];
        }
#pragma unroll
        for (int kk = 0; kk < 8; kk++) {
            ulonglong2 a0 = *(const ulonglong2*)&As[cur][kk][ty * 8];
            ulonglong2 a1 = *(const ulonglong2*)&As[cur][kk][ty * 8 + 4];
            unsigned long long av[4] = { a0.x, a0.y, a1.x, a1.y };
            ulonglong2 b0 = *(const ulonglong2*)&Bs[cur][kk][tx * 8 + 0];
            ulonglong2 b1 = *(const ulonglong2*)&Bs[cur][kk][tx * 8 + 2];
            ulonglong2 b2 = *(const ulonglong2*)&Bs[cur][kk][tx * 8 + 4];
            ulonglong2 b3 = *(const ulonglong2*)&Bs[cur][kk][tx * 8 + 6];
            unsigned long long bv[8] = { b0.x, b0.y, b1.x, b1.y, b2.x, b2.y, b3.x, b3.y };
#pragma unroll
            for (int i = 0; i < 4; i++)
#pragma unroll
                for (int j = 0; j < 8; j++)
                    FMA2(acc[i][j], av[i], bv[j]);
        }
        if (has) {
            const int nxt = cur ^ 1;
            As[nxt][akk + 0][arow] = pa.x; As[nxt][akk + 1][arow] = pa.y;
            As[nxt][akk + 2][arow] = pa.z; As[nxt][akk + 3][arow] = pa.w;
            *(float4*)&Bs[nxt][bkr][bnc + 0] = make_float4(pw.x, pw.x, pw.y, pw.y);
            *(float4*)&Bs[nxt][bkr][bnc + 2] = make_float4(pw.z, pw.z, pw.w, pw.w);
        }
        __syncthreads();
    }

    float bias8[8];
#pragma unroll
    for (int j = 0; j < 8; j++) bias8[j] = bias[hc0 + tx * 8 + j];

    float* gout = g_xproj + (size_t)gate * TBH;
#pragma unroll
    for (int i = 0; i < 4; i++) {
#pragma unroll
        for (int half = 0; half < 2; half++) {
            const int r  = rb + ty * 8 + i * 2 + half;
            const int t  = r & (Tseq - 1);
            const int bb = r >> 9;
            float* dst = gout + ((size_t)(t * Bsz + bb)) * Hdim + hc0 + tx * 8;
            float v[8];
#pragma unroll
            for (int j = 0; j < 8; j++)
                v[j] = (half ? f2hi(acc[i][j]) : f2lo(acc[i][j])) + bias8[j];
            *(float4*)&dst[0] = make_float4(v[0], v[1], v[2], v[3]);
            *(float4*)&dst[4] = make_float4(v[4], v[5], v[6], v[7]);
        }
    }
}

// ---------------- persistent recurrence ----------------
// smem: [0,65536) h tiles 2x[128][64]f | [65536,98304) w tiles 2x[128][32]f
//       [98304,163840) PART u64 (p1: [8][32][32], p2: [8][16][32]) + SHN staging
#define SMEM_BYTES 163840

__global__ void __launch_bounds__(NT, 1) gru_rec_kernel(
    const float* __restrict__ Whu, const float* __restrict__ Whr,
    const float* __restrict__ Whh, float* __restrict__ out)
{
    extern __shared__ char smem_raw[];
    float* SH = (float*)smem_raw;
    float* SW = (float*)(smem_raw + 65536);
    unsigned long long* PART = (unsigned long long*)(smem_raw + 98304);
    float* SHN = (float*)(smem_raw + 98304 + 32768);   // [16 n][64 b]

    const int tid  = threadIdx.x;
    const int cta  = blockIdx.x;
    const int ws   = tid >> 5;            // warp = k-slice (0..7)
    const int lane = tid & 31;
    const int bpos = lane & 7;            // 8 b-groups of 8
    const int npos = lane >> 3;           // 4 n-groups

    const int bhalf = cta & 1, bbase = bhalf * 64;
    const int ngrp  = cta >> 1;           // 0..63
    const int isR   = ngrp >= 32;
    const float* __restrict__ Wzr = isR ? Whr : Whu;
    const int col1  = (ngrp & 31) * 32;   // phase1 n base (32 cols)
    const int n2    = ngrp * 16;          // phase2 n base (16 cols)

    for (int t = 0; t < Tseq; t++) {
        // ======================= phase 1 : z / r =======================
        unsigned long long acc[8][4];
#pragma unroll
        for (int j = 0; j < 8; j++)
#pragma unroll
            for (int i = 0; i < 4; i++) acc[j][i] = 0ULL;

        {
#pragma unroll
            for (int q = 0; q < 8; q++) {              // h: [128][64]f = 2048 f4
                int idx = tid + q * NT;
                int row = idx >> 4, c4 = (idx & 15) * 4;
                cp16(SH + row * 64 + c4, g_hT + (size_t)row * Bsz + bbase + c4);
            }
#pragma unroll
            for (int q = 0; q < 4; q++) {              // w: [128][32]f = 1024 f4
                int idx = tid + q * NT;
                int row = idx >> 3, c4 = (idx & 7) * 4;
                cp16(SW + row * 32 + c4, Wzr + (size_t)row * Hdim + col1 + c4);
            }
            CP_COMMIT();
        }

        int buf = 0;
        for (int cc = 0; cc < 8; cc++) {
            if (cc < 7) {
                const int k0 = (cc + 1) * KC;
                const int ob = buf ^ 1;
#pragma unroll
                for (int q = 0; q < 8; q++) {
                    int idx = tid + q * NT;
                    int row = idx >> 4, c4 = (idx & 15) * 4;
                    cp16(SH + (size_t)(ob * KC + row) * 64 + c4,
                         g_hT + (size_t)(k0 + row) * Bsz + bbase + c4);
                }
#pragma unroll
                for (int q = 0; q < 4; q++) {
                    int idx = tid + q * NT;
                    int row = idx >> 3, c4 = (idx & 7) * 4;
                    cp16(SW + (size_t)(ob * KC + row) * 32 + c4,
                         Wzr + (size_t)(k0 + row) * Hdim + col1 + c4);
                }
                CP_COMMIT();
                CP_WAIT1();
            } else {
                CP_WAIT0();
            }
            __syncthreads();

            const float* hb = SH + buf * 8192;
            const float* wb = SW + buf * 4096;
#pragma unroll 8
            for (int kk = 0; kk < 16; kk++) {
                const int kr = (ws << 4) + kk;
                const float* hr = hb + kr * 64 + bpos * 8;
                ulonglong2 hA = *(const ulonglong2*)(hr);
                ulonglong2 hB = *(const ulonglong2*)(hr + 4);
                const float* wr = wb + kr * 32 + npos * 8;
                float4 w0 = *(const float4*)(wr);
                float4 w1 = *(const float4*)(wr + 4);
                unsigned long long wd[8] = {
                    dup2(w0.x), dup2(w0.y), dup2(w0.z), dup2(w0.w),
                    dup2(w1.x), dup2(w1.y), dup2(w1.z), dup2(w1.w) };
#pragma unroll
                for (int j = 0; j < 8; j++) {
                    FMA2(acc[j][0], hA.x, wd[j]);
                    FMA2(acc[j][1], hA.y, wd[j]);
                    FMA2(acc[j][2], hB.x, wd[j]);
                    FMA2(acc[j][3], hB.y, wd[j]);
                }
            }
            __syncthreads();
            buf ^= 1;
        }

        // partials: PART[ws][n_local(32)][bpair(32)]
#pragma unroll
        for (int j = 0; j < 8; j++)
#pragma unroll
            for (int i = 0; i < 4; i++)
                PART[((size_t)(ws << 5) + npos * 8 + j) * 32 + bpos * 4 + i] = acc[j][i];
        __syncthreads();

        // epilogue: thread -> n = tid>>3 (32), local-b run = (tid&7)*8
        {
            const int n  = tid >> 3;
            const int b8 = (tid & 7) * 8;
            float s[8];
#pragma unroll
            for (int i4 = 0; i4 < 4; i4++) {
                float sx = 0.f, sy = 0.f;
#pragma unroll
                for (int w = 0; w < 8; w++) {
                    unsigned long long p = PART[((size_t)(w << 5) + n) * 32 + (b8 >> 1) + i4];
                    sx += f2lo(p); sy += f2hi(p);
                }
                s[2 * i4] = sx; s[2 * i4 + 1] = sy;
            }
            const int nn = col1 + n;
            const int bb = bbase + b8;
            const float* xg = g_xproj + (isR ? TBH : (size_t)0) + (size_t)t * BH;
#pragma unroll
            for (int e = 0; e < 8; e++)
                s[e] = sigmoidf_(s[e] + __ldcs(&xg[(size_t)(bb + e) * Hdim + nn]));
            if (!isR) {
                *(float4*)&g_zT[nn * Bsz + bb]     = make_float4(s[0], s[1], s[2], s[3]);
                *(float4*)&g_zT[nn * Bsz + bb + 4] = make_float4(s[4], s[5], s[6], s[7]);
            } else {
                float4 h0 = __ldcg((const float4*)&g_hT[nn * Bsz + bb]);
                float4 h1 = __ldcg((const float4*)&g_hT[nn * Bsz + bb + 4]);
                *(float4*)&g_rhT[nn * Bsz + bb] =
                    make_float4(s[0] * h0.x, s[1] * h0.y, s[2] * h0.z, s[3] * h0.w);
                *(float4*)&g_rhT[nn * Bsz + bb + 4] =
                    make_float4(s[4] * h1.x, s[5] * h1.y, s[6] * h1.z, s[7] * h1.w);
            }
        }
        grid_sync();

        // ======================= phase 2 : candidate + update =======================
        unsigned long long ac2[4][4];
#pragma unroll
        for (int j = 0; j < 4; j++)
#pragma unroll
            for (int i = 0; i < 4; i++) ac2[j][i] = 0ULL;

        {
#pragma unroll
            for (int q = 0; q < 8; q++) {
                int idx = tid + q * NT;
                int row = idx >> 4, c4 = (idx & 15) * 4;
                cp16(SH + row * 64 + c4, g_rhT + (size_t)row * Bsz + bbase + c4);
            }
#pragma unroll
            for (int q = 0; q < 2; q++) {              // w2: [128][16]f = 512 f4
                int idx = tid + q * NT;
                int row = idx >> 2, c4 = (idx & 3) * 4;
                cp16(SW + row * 16 + c4, Whh + (size_t)row * Hdim + n2 + c4);
            }
            CP_COMMIT();
        }

        buf = 0;
        for (int cc = 0; cc < 8; cc++) {
            if (cc < 7) {
                const int k0 = (cc + 1) * KC;
                const int ob = buf ^ 1;
#pragma unroll
                for (int q = 0; q < 8; q++) {
                    int idx = tid + q * NT;
                    int row = idx >> 4, c4 = (idx & 15) * 4;
                    cp16(SH + (size_t)(ob * KC + row) * 64 + c4,
                         g_rhT + (size_t)(k0 + row) * Bsz + bbase + c4);
                }
#pragma unroll
                for (int q = 0; q < 2; q++) {
                    int idx = tid + q * NT;
                    int row = idx >> 2, c4 = (idx & 3) * 4;
                    cp16(SW + (size_t)(ob * KC + row) * 16 + c4,
                         Whh + (size_t)(k0 + row) * Hdim + n2 + c4);
                }
                CP_COMMIT();
                CP_WAIT1();
            } else {
                CP_WAIT0();
            }
            __syncthreads();

            const float* hb = SH + buf * 8192;
            const float* wb = SW + buf * 2048;
#pragma unroll 8
            for (int kk = 0; kk < 16; kk++) {
                const int kr = (ws << 4) + kk;
                const float* hr = hb + kr * 64 + bpos * 8;
                ulonglong2 hA = *(const ulonglong2*)(hr);
                ulonglong2 hB = *(const ulonglong2*)(hr + 4);
                float4 w4 = *(const float4*)(wb + kr * 16 + npos * 4);
                unsigned long long wd[4] = { dup2(w4.x), dup2(w4.y), dup2(w4.z), dup2(w4.w) };
#pragma unroll
                for (int j = 0; j < 4; j++) {
                    FMA2(ac2[j][0], hA.x, wd[j]);
                    FMA2(ac2[j][1], hA.y, wd[j]);
                    FMA2(ac2[j][2], hB.x, wd[j]);
                    FMA2(ac2[j][3], hB.y, wd[j]);
                }
            }
            __syncthreads();
            buf ^= 1;
        }

        // partials: PART[ws][n_local(16)][bpair(32)]
#pragma unroll
        for (int j = 0; j < 4; j++)
#pragma unroll
            for (int i = 0; i < 4; i++)
                PART[((size_t)(ws << 4) + npos * 4 + j) * 32 + bpos * 4 + i] = ac2[j][i];
        __syncthreads();

        // epilogue: thread -> n = tid>>4 (16), b run = (tid&15)*4
        {
            const int n  = tid >> 4;
            const int b4 = (tid & 15) * 4;
            float s[4];
#pragma unroll
            for (int i2 = 0; i2 < 2; i2++) {
                float sx = 0.f, sy = 0.f;
#pragma unroll
                for (int w = 0; w < 8; w++) {
                    unsigned long long p = PART[((size_t)(w << 4) + n) * 32 + (b4 >> 1) + i2];
                    sx += f2lo(p); sy += f2hi(p);
                }
                s[2 * i2] = sx; s[2 * i2 + 1] = sy;
            }
            const int nn = n2 + n;
            const int bb = bbase + b4;
            const float* xh = g_xproj + 2 * TBH + (size_t)t * BH;
            float4 z4 = __ldcg((const float4*)&g_zT[nn * Bsz + bb]);
            float4 h4 = __ldcg((const float4*)&g_hT[nn * Bsz + bb]);
            float zz[4] = { z4.x, z4.y, z4.z, z4.w };
            float hh[4] = { h4.x, h4.y, h4.z, h4.w };
            float hn[4];
#pragma unroll
            for (int e = 0; e < 4; e++) {
                float c = tanhf(s[e] + __ldcs(&xh[(size_t)(bb + e) * Hdim + nn]));
                hn[e] = hh[e] + zz[e] * (c - hh[e]);
            }
            *(float4*)&g_hT[nn * Bsz + bb] = make_float4(hn[0], hn[1], hn[2], hn[3]);
            // stage for coalesced out write: SHN[n][b_local]
#pragma unroll
            for (int e = 0; e < 4; e++)
                SHN[n * 64 + b4 + e] = hn[e];
        }
        __syncthreads();
        if (out) {
            const int b  = tid >> 2;          // 0..63
            const int nq = (tid & 3) * 4;     // 0,4,8,12
            float4 v = make_float4(SHN[(nq + 0) * 64 + b], SHN[(nq + 1) * 64 + b],
                                   SHN[(nq + 2) * 64 + b], SHN[(nq + 3) * 64 + b]);
            *(float4*)&out[(size_t)t * BH + (size_t)(bbase + b) * Hdim + n2 + nq] = v;
        }
        grid_sync();
    }
}

// ---------------- final hidden state ----------------
__global__ void hlast_kernel(float* __restrict__ dst) {
    int i = blockIdx.x * 256 + threadIdx.x;
    int b = i >> 10;
    int k = i & (Hdim - 1);
    dst[i] = g_hT[k * Bsz + b];
}

// ---------------- launch ----------------
extern "C" void kernel_launch(void* const* d_in, const int* in_sizes, int n_in,
                              void* d_out, int out_size)
{
    (void)in_sizes; (void)n_in;
    const float* x   = (const float*)d_in[0];
    const float* h0  = (const float*)d_in[1];
    const float* Wiu = (const float*)d_in[2];
    const float* Whu = (const float*)d_in[3];
    const float* bu  = (const float*)d_in[4];
    const float* Wir = (const float*)d_in[5];
    const float* Whr = (const float*)d_in[6];
    const float* br  = (const float*)d_in[7];
    const float* Wih = (const float*)d_in[8];
    const float* Whh = (const float*)d_in[9];
    const float* bh  = (const float*)d_in[10];
    float* out = (float*)d_out;

    const bool write_seq  = ((size_t)out_size >= TBH);
    const bool write_last = ((size_t)out_size >= TBH + (size_t)Bsz * Hdim);

    cudaFuncSetAttribute(gru_rec_kernel,
                         cudaFuncAttributeMaxDynamicSharedMemorySize, SMEM_BYTES);

    init_h_kernel<<<512, 256>>>(h0);

    dim3 pg(65536 / 128, 3072 / 128);
    proj_kernel<<<pg, 256>>>(x, Wiu, Wir, Wih, bu, br, bh);

    gru_rec_kernel<<<NC, NT, SMEM_BYTES>>>(Whu, Whr, Whh, write_seq ? out : nullptr);

    if (write_last)        hlast_kernel<<<512, 256>>>(out + TBH);
    else if (!write_seq)   hlast_kernel<<<512, 256>>>(out);
}

// round 6
// speedup vs baseline: 2.1735x; 1.2664x over previous
#include <cuda_runtime.h>
#include <cuda_bf16.h>
#include <cstdint>

#define Bsz  128
#define Tseq 512
#define Din  512
#define Hdim 1024
#define BH   (Bsz * Hdim)
#define TBH  ((size_t)Tseq * (size_t)Bsz * (size_t)Hdim)
#define NC   128
#define NT   256

// ---------------- static device scratch ----------------
__device__ float g_xproj[3ULL * 512ULL * 128ULL * 1024ULL]; // (gate, t, b, h)
__device__ float g_h[BH];                 // h fp32, [b][k]
__device__ float g_z[BH];                 // z gate fp32, [b][n]
__device__ uint32_t g_hbfu [2][BH / 2];   // h  bf16 hi/lo, [b][k/2] packed pairs
__device__ uint32_t g_rhbfu[2][BH / 2];   // r*h bf16 hi/lo
__device__ uint32_t g_WzrF[2][256][64][32][2]; // B-frags [hl][ntile][k16][lane][reg]
__device__ uint32_t g_WhhF[2][128][64][32][2];
__device__ unsigned int g_bar = 0;

// ---------------- helpers ----------------
#define FMA2(d, a, b) asm("fma.rn.f32x2 %0, %1, %2, %0;" : "+l"(d) : "l"(a), "l"(b))
__device__ __forceinline__ float f2lo(unsigned long long v) { return __uint_as_float((unsigned)v); }
__device__ __forceinline__ float f2hi(unsigned long long v) { return __uint_as_float((unsigned)(v >> 32)); }
__device__ __forceinline__ float sigmoidf_(float x) { return 1.0f / (1.0f + __expf(-x)); }

__device__ __forceinline__ void bsplit(float v, __nv_bfloat16& hi, __nv_bfloat16& lo) {
    hi = __float2bfloat16(v);
    lo = __float2bfloat16(v - __bfloat162float(hi));
}
__device__ __forceinline__ uint32_t packbf(__nv_bfloat16 a, __nv_bfloat16 b) {
    unsigned short x = *(unsigned short*)&a, y = *(unsigned short*)&b;
    return (uint32_t)x | ((uint32_t)y << 16);
}

__device__ __forceinline__ void cp16(uint32_t s, const void* g) {
    asm volatile("cp.async.cg.shared.global [%0], [%1], 16;" :: "r"(s), "l"(g));
}
#define CP_COMMIT() asm volatile("cp.async.commit_group;")
#define CP_WAIT1()  asm volatile("cp.async.wait_group 1;")
#define CP_WAIT0()  asm volatile("cp.async.wait_group 0;")

__device__ __forceinline__ void grid_sync() {
    __syncthreads();
    if (threadIdx.x == 0) {
        __threadfence();
        unsigned int old = atomicAdd(&g_bar, 1u);
        unsigned int target = (old / NC + 1u) * NC;
        unsigned int v;
        do {
            asm volatile("ld.acquire.gpu.global.u32 %0, [%1];"
                         : "=r"(v) : "l"(&g_bar) : "memory");
        } while (v < target);
    }
    __syncthreads();
}

__device__ __forceinline__ void ldsm4(uint32_t (&r)[4], uint32_t a) {
    asm volatile("ldmatrix.sync.aligned.m8n8.x4.shared.b16 {%0,%1,%2,%3}, [%4];"
                 : "=r"(r[0]), "=r"(r[1]), "=r"(r[2]), "=r"(r[3]) : "r"(a));
}
__device__ __forceinline__ void mma16816(float (&d)[4], const uint32_t (&a)[4],
                                         uint32_t b0, uint32_t b1) {
    asm volatile(
        "mma.sync.aligned.m16n8k16.row.col.f32.bf16.bf16.f32 "
        "{%0,%1,%2,%3}, {%4,%5,%6,%7}, {%8,%9}, {%0,%1,%2,%3};"
        : "+f"(d[0]), "+f"(d[1]), "+f"(d[2]), "+f"(d[3])
        : "r"(a[0]), "r"(a[1]), "r"(a[2]), "r"(a[3]), "r"(b0), "r"(b1));
}

// ---------------- setup kernels ----------------
__global__ void init_h_kernel(const float* __restrict__ h0) {
    int i = blockIdx.x * 256 + threadIdx.x;        // BH/2
    int b = i >> 9, kp = i & 511;
    float2 v = *(const float2*)&h0[(size_t)b * Hdim + kp * 2];
    *(float2*)&g_h[(size_t)b * Hdim + kp * 2] = v;
    __nv_bfloat16 h0a, l0a, h1a, l1a;
    bsplit(v.x, h0a, l0a); bsplit(v.y, h1a, l1a);
    g_hbfu[0][(size_t)b * 512 + kp] = packbf(h0a, h1a);
    g_hbfu[1][(size_t)b * 512 + kp] = packbf(l0a, l1a);
}

__global__ void pack_wzrF_kernel(const float* __restrict__ Whu, const float* __restrict__ Whr) {
    int i = blockIdx.x * 256 + threadIdx.x;        // 1,048,576
    int reg = i & 1, lane = (i >> 1) & 31, k16 = (i >> 6) & 63, nt = i >> 12;
    int n = nt * 8 + (lane >> 2);
    int k = k16 * 16 + reg * 8 + (lane & 3) * 2;
    const float* W = (n < Hdim) ? Whu : Whr;
    int nn = n & (Hdim - 1);
    float v0 = W[(size_t)k * Hdim + nn];
    float v1 = W[(size_t)(k + 1) * Hdim + nn];
    __nv_bfloat16 h0a, l0a, h1a, l1a;
    bsplit(v0, h0a, l0a); bsplit(v1, h1a, l1a);
    g_WzrF[0][nt][k16][lane][reg] = packbf(h0a, h1a);
    g_WzrF[1][nt][k16][lane][reg] = packbf(l0a, l1a);
}

__global__ void pack_whhF_kernel(const float* __restrict__ Whh) {
    int i = blockIdx.x * 256 + threadIdx.x;        // 524,288
    int reg = i & 1, lane = (i >> 1) & 31, k16 = (i >> 6) & 63, nt = i >> 12;
    int n = nt * 8 + (lane >> 2);
    int k = k16 * 16 + reg * 8 + (lane & 3) * 2;
    float v0 = Whh[(size_t)k * Hdim + n];
    float v1 = Whh[(size_t)(k + 1) * Hdim + n];
    __nv_bfloat16 h0a, l0a, h1a, l1a;
    bsplit(v0, h0a, l0a); bsplit(v1, h1a, l1a);
    g_WhhF[0][nt][k16][lane][reg] = packbf(h0a, h1a);
    g_WhhF[1][nt][k16][lane][reg] = packbf(l0a, l1a);
}

// ---------------- phase A: x @ [Wiu|Wir|Wih] + bias (fp32 SIMT) ----------------
__global__ void __launch_bounds__(256, 2) proj_kernel(
    const float* __restrict__ x,
    const float* __restrict__ Wiu, const float* __restrict__ Wir, const float* __restrict__ Wih,
    const float* __restrict__ bu,  const float* __restrict__ br,  const float* __restrict__ bh)
{
    __shared__ float  As[2][8][128];
    __shared__ float2 Bs[2][8][128];

    const int tid = threadIdx.x;
    const int rb  = blockIdx.x * 128;
    const int cb  = blockIdx.y * 128;
    const int gate = cb >> 10;
    const int hc0  = cb & (Hdim - 1);
    const float* W    = (gate == 0) ? Wiu : (gate == 1 ? Wir : Wih);
    const float* bias = (gate == 0) ? bu  : (gate == 1 ? br  : bh);

    const int arow = tid >> 1;
    const int akk  = (tid & 1) * 4;
    const int bkr  = tid >> 5;
    const int bnc  = (tid & 31) * 4;
    const int tx = tid & 15, ty = tid >> 4;

    unsigned long long acc[4][8];
#pragma unroll
    for (int i = 0; i < 4; i++)
#pragma unroll
        for (int j = 0; j < 8; j++) acc[i][j] = 0ULL;

    {
        float4 a = *(const float4*)&x[(size_t)(rb + arow) * Din + akk];
        float4 w = *(const float4*)&W[(size_t)bkr * Hdim + hc0 + bnc];
        As[0][akk + 0][arow] = a.x; As[0][akk + 1][arow] = a.y;
        As[0][akk + 2][arow] = a.z; As[0][akk + 3][arow] = a.w;
        *(float4*)&Bs[0][bkr][bnc + 0] = make_float4(w.x, w.x, w.y, w.y);
        *(float4*)&Bs[0][bkr][bnc + 2] = make_float4(w.z, w.z, w.w, w.w);
    }
    __syncthreads();

    const int nsteps = Din / 8;
    for (int ks = 0; ks < nsteps; ks++) {
        const int cur = ks & 1;
        float4 pa, pw;
        const bool has = (ks + 1 < nsteps);
        if (has) {
            pa = *(const float4*)&x[(size_t)(rb + arow) * Din + (ks + 1) * 8 + akk];
            pw = *(const float4*)&W[(size_t)((ks + 1) * 8 + bkr) * Hdim + hc0 + bnc];
        }
#pragma unroll
        for (int kk = 0; kk < 8; kk++) {
            ulonglong2 a0 = *(const ulonglong2*)&As[cur][kk][ty * 8];
            ulonglong2 a1 = *(const ulonglong2*)&As[cur][kk][ty * 8 + 4];
            unsigned long long av[4] = { a0.x, a0.y, a1.x, a1.y };
            ulonglong2 b0 = *(const ulonglong2*)&Bs[cur][kk][tx * 8 + 0];
            ulonglong2 b1 = *(const ulonglong2*)&Bs[cur][kk][tx * 8 + 2];
            ulonglong2 b2 = *(const ulonglong2*)&Bs[cur][kk][tx * 8 + 4];
            ulonglong2 b3 = *(const ulonglong2*)&Bs[cur][kk][tx * 8 + 6];
            unsigned long long bv[8] = { b0.x, b0.y, b1.x, b1.y, b2.x, b2.y, b3.x, b3.y };
#pragma unroll
            for (int i = 0; i < 4; i++)
#pragma unroll
                for (int j = 0; j < 8; j++)
                    FMA2(acc[i][j], av[i], bv[j]);
        }
        if (has) {
            const int nxt = cur ^ 1;
            As[nxt][akk + 0][arow] = pa.x; As[nxt][akk + 1][arow] = pa.y;
            As[nxt][akk + 2][arow] = pa.z; As[nxt][akk + 3][arow] = pa.w;
            *(float4*)&Bs[nxt][bkr][bnc + 0] = make_float4(pw.x, pw.x, pw.y, pw.y);
            *(float4*)&Bs[nxt][bkr][bnc + 2] = make_float4(pw.z, pw.z, pw.w, pw.w);
        }
        __syncthreads();
    }

    float bias8[8];
#pragma unroll
    for (int j = 0; j < 8; j++) bias8[j] = bias[hc0 + tx * 8 + j];

    float* gout = g_xproj + (size_t)gate * TBH;
#pragma unroll
    for (int i = 0; i < 4; i++) {
#pragma unroll
        for (int half = 0; half < 2; half++) {
            const int r  = rb + ty * 8 + i * 2 + half;
            const int t  = r & (Tseq - 1);
            const int bb = r >> 9;
            float* dst = gout + ((size_t)(t * Bsz + bb)) * Hdim + hc0 + tx * 8;
            float v[8];
#pragma unroll
            for (int j = 0; j < 8; j++)
                v[j] = (half ? f2hi(acc[i][j]) : f2lo(acc[i][j])) + bias8[j];
            *(float4*)&dst[0] = make_float4(v[0], v[1], v[2], v[3]);
            *(float4*)&dst[4] = make_float4(v[4], v[5], v[6], v[7]);
        }
    }
}

// ---------------- persistent recurrence (mma.sync bf16 3-pass) ----------------
__global__ void __launch_bounds__(NT, 1) gru_rec_kernel(float* __restrict__ out)
{
    __shared__ char smA[32768];   // 2 buf x 2 hl x [64 rows][128B SW128]
    const uint32_t smb = (uint32_t)__cvta_generic_to_shared(smA);

    const int tid  = threadIdx.x, cta = blockIdx.x;
    const int wid  = tid >> 5, lane = tid & 31;
    const int gid  = lane >> 2, t4 = lane & 3;
    const int bhalf = cta & 1, bbase = bhalf * 64;
    const int ngrp  = cta >> 1;            // 0..63
    const int isR   = ngrp >= 32;

    // phase1 warp mapping: (mg 0-1) x (nq 0-3)
    const int mg = wid & 1, nq = wid >> 1;
    const int ntile1 = ngrp * 4 + nq;      // 0..255
    // phase2: (mt2 0-3) x (nt2 0-1)
    const int mt2 = wid >> 1, nt2 = wid & 1;
    const int ntile2 = ngrp * 2 + nt2;     // 0..127

    // ldmatrix per-lane terms
    const int lrowoff = ((lane >> 3) & 1) * 8 + (lane & 7);
    const int lkq  = lane >> 4;            // col-half (k 0-7 / 8-15)
    const int lsw  = (lane & 7) * 16;

    auto load_chunk = [&](int buf, int k0, const uint32_t* s0, const uint32_t* s1) {
#pragma unroll
        for (int q = 0; q < 4; q++) {
            int u = tid + q * NT;
            int hl = u >> 9, rem = u & 511;
            int row = rem >> 3, cu = rem & 7;
            uint32_t dst = smb + buf * 16384 + hl * 8192 + row * 128
                         + ((cu * 16) ^ ((row & 7) * 16));
            const uint32_t* s = (hl ? s1 : s0)
                              + (size_t)(bbase + row) * 512 + (k0 >> 1) + cu * 4;
            cp16(dst, s);
        }
        CP_COMMIT();
    };

    for (int t = 0; t < Tseq; t++) {
        // ================= phase 1 : z / r =================
        float acc[2][4];
#pragma unroll
        for (int m = 0; m < 2; m++)
#pragma unroll
            for (int i = 0; i < 4; i++) acc[m][i] = 0.f;

        load_chunk(0, 0, g_hbfu[0], g_hbfu[1]);
        for (int c = 0; c < 16; c++) {
            const int buf = c & 1;
            unsigned long long Bh[4], Bl[4];
#pragma unroll
            for (int i = 0; i < 4; i++) {
                Bh[i] = *(const unsigned long long*)&g_WzrF[0][ntile1][c * 4 + i][lane][0];
                Bl[i] = *(const unsigned long long*)&g_WzrF[1][ntile1][c * 4 + i][lane][0];
            }
            if (c < 15) { load_chunk(buf ^ 1, (c + 1) * 64, g_hbfu[0], g_hbfu[1]); CP_WAIT1(); }
            else        { CP_WAIT0(); }
            __syncthreads();

            const uint32_t base = smb + buf * 16384;
#pragma unroll
            for (int kl = 0; kl < 4; kl++) {
                const uint32_t bcol = (uint32_t)((kl * 32 + lkq * 16) ^ lsw);
                uint32_t Ah[2][4], Al[2][4];
#pragma unroll
                for (int mt = 0; mt < 2; mt++) {
                    const int mtile = mg * 2 + mt;
                    uint32_t ra = base + (uint32_t)((mtile * 16 + lrowoff) * 128) + bcol;
                    ldsm4(Ah[mt], ra);
                    ldsm4(Al[mt], ra + 8192);
                }
                const uint32_t bh0 = (uint32_t)Bh[kl], bh1 = (uint32_t)(Bh[kl] >> 32);
                const uint32_t bl0 = (uint32_t)Bl[kl], bl1 = (uint32_t)(Bl[kl] >> 32);
#pragma unroll
                for (int mt = 0; mt < 2; mt++) {
                    mma16816(acc[mt], Ah[mt], bh0, bh1);
                    mma16816(acc[mt], Ah[mt], bl0, bl1);
                    mma16816(acc[mt], Al[mt], bh0, bh1);
                }
            }
            __syncthreads();
        }

        // phase1 epilogue
        {
            const float* xg = g_xproj + (isR ? TBH : (size_t)0) + (size_t)t * BH;
            const int Ncol = ngrp * 32 + nq * 8 + t4 * 2;
#pragma unroll
            for (int mt = 0; mt < 2; mt++) {
                const int mtile = mg * 2 + mt;
#pragma unroll
                for (int hf = 0; hf < 2; hf++) {
                    const int b = bbase + mtile * 16 + gid + hf * 8;
                    const float dx = acc[mt][hf * 2], dy = acc[mt][hf * 2 + 1];
                    if (!isR) {
                        float2 xu = __ldcs((const float2*)(xg + (size_t)b * Hdim + Ncol));
                        float2 zv;
                        zv.x = sigmoidf_(dx + xu.x);
                        zv.y = sigmoidf_(dy + xu.y);
                        *(float2*)&g_z[(size_t)b * Hdim + Ncol] = zv;
                    } else {
                        const int j = Ncol - Hdim;
                        float2 xr = __ldcs((const float2*)(xg + (size_t)b * Hdim + j));
                        float2 h2 = __ldcg((const float2*)&g_h[(size_t)b * Hdim + j]);
                        float r0 = sigmoidf_(dx + xr.x) * h2.x;
                        float r1 = sigmoidf_(dy + xr.y) * h2.y;
                        __nv_bfloat16 H0, L0, H1, L1;
                        bsplit(r0, H0, L0); bsplit(r1, H1, L1);
                        g_rhbfu[0][(size_t)b * 512 + (j >> 1)] = packbf(H0, H1);
                        g_rhbfu[1][(size_t)b * 512 + (j >> 1)] = packbf(L0, L1);
                    }
                }
            }
        }
        grid_sync();

        // ================= phase 2 : candidate + update =================
        float ac2[4] = { 0.f, 0.f, 0.f, 0.f };
        load_chunk(0, 0, g_rhbfu[0], g_rhbfu[1]);
        for (int c = 0; c < 16; c++) {
            const int buf = c & 1;
            unsigned long long Bh[4], Bl[4];
#pragma unroll
            for (int i = 0; i < 4; i++) {
                Bh[i] = *(const unsigned long long*)&g_WhhF[0][ntile2][c * 4 + i][lane][0];
                Bl[i] = *(const unsigned long long*)&g_WhhF[1][ntile2][c * 4 + i][lane][0];
            }
            if (c < 15) { load_chunk(buf ^ 1, (c + 1) * 64, g_rhbfu[0], g_rhbfu[1]); CP_WAIT1(); }
            else        { CP_WAIT0(); }
            __syncthreads();

            const uint32_t base = smb + buf * 16384;
#pragma unroll
            for (int kl = 0; kl < 4; kl++) {
                const uint32_t bcol = (uint32_t)((kl * 32 + lkq * 16) ^ lsw);
                uint32_t Ah[4], Al[4];
                uint32_t ra = base + (uint32_t)((mt2 * 16 + lrowoff) * 128) + bcol;
                ldsm4(Ah, ra);
                ldsm4(Al, ra + 8192);
                const uint32_t bh0 = (uint32_t)Bh[kl], bh1 = (uint32_t)(Bh[kl] >> 32);
                const uint32_t bl0 = (uint32_t)Bl[kl], bl1 = (uint32_t)(Bl[kl] >> 32);
                mma16816(ac2, Ah, bh0, bh1);
                mma16816(ac2, Ah, bl0, bl1);
                mma16816(ac2, Al, bh0, bh1);
            }
            __syncthreads();
        }

        // phase2 epilogue
        {
            const float* xh = g_xproj + 2 * TBH + (size_t)t * BH;
            const int n = ngrp * 16 + nt2 * 8 + t4 * 2;
#pragma unroll
            for (int hf = 0; hf < 2; hf++) {
                const int b = bbase + mt2 * 16 + gid + hf * 8;
                float2 xv = __ldcs((const float2*)(xh + (size_t)b * Hdim + n));
                float2 zv = __ldcg((const float2*)&g_z[(size_t)b * Hdim + n]);
                float2 hv = __ldcg((const float2*)&g_h[(size_t)b * Hdim + n]);
                float c0 = tanhf(ac2[hf * 2]     + xv.x);
                float c1 = tanhf(ac2[hf * 2 + 1] + xv.y);
                float hn0 = hv.x + zv.x * (c0 - hv.x);
                float hn1 = hv.y + zv.y * (c1 - hv.y);
                *(float2*)&g_h[(size_t)b * Hdim + n] = make_float2(hn0, hn1);
                __nv_bfloat16 H0, L0, H1, L1;
                bsplit(hn0, H0, L0); bsplit(hn1, H1, L1);
                g_hbfu[0][(size_t)b * 512 + (n >> 1)] = packbf(H0, H1);
                g_hbfu[1][(size_t)b * 512 + (n >> 1)] = packbf(L0, L1);
                if (out)
                    *(float2*)&out[(size_t)t * BH + (size_t)b * Hdim + n] = make_float2(hn0, hn1);
            }
        }
        grid_sync();
    }
}

// ---------------- final hidden state ----------------
__global__ void hlast_kernel(float* __restrict__ dst) {
    int i = blockIdx.x * 256 + threadIdx.x;
    dst[i] = g_h[i];
}

// ---------------- launch ----------------
extern "C" void kernel_launch(void* const* d_in, const int* in_sizes, int n_in,
                              void* d_out, int out_size)
{
    (void)in_sizes; (void)n_in;
    const float* x   = (const float*)d_in[0];
    const float* h0  = (const float*)d_in[1];
    const float* Wiu = (const float*)d_in[2];
    const float* Whu = (const float*)d_in[3];
    const float* bu  = (const float*)d_in[4];
    const float* Wir = (const float*)d_in[5];
    const float* Whr = (const float*)d_in[6];
    const float* br  = (const float*)d_in[7];
    const float* Wih = (const float*)d_in[8];
    const float* Whh = (const float*)d_in[9];
    const float* bh  = (const float*)d_in[10];
    float* out = (float*)d_out;

    const bool write_seq  = ((size_t)out_size >= TBH);
    const bool write_last = ((size_t)out_size >= TBH + (size_t)Bsz * Hdim);

    init_h_kernel<<<BH / 512, 256>>>(h0);
    pack_wzrF_kernel<<<4096, 256>>>(Whu, Whr);
    pack_whhF_kernel<<<2048, 256>>>(Whh);

    dim3 pg(65536 / 128, 3072 / 128);
    proj_kernel<<<pg, 256>>>(x, Wiu, Wir, Wih, bu, br, bh);

    gru_rec_kernel<<<NC, NT>>>(write_seq ? out : nullptr);

    if (write_last)        hlast_kernel<<<BH / 256, 256>>>(out + TBH);
    else if (!write_seq)   hlast_kernel<<<BH / 256, 256>>>(out);
}

// round 7
// speedup vs baseline: 3.0142x; 1.3868x over previous
#include <cuda_runtime.h>
#include <cuda_bf16.h>
#include <cstdint>

#define Bsz  128
#define Tseq 512
#define Din  512
#define Hdim 1024
#define BH   (Bsz * Hdim)
#define TBH  ((size_t)Tseq * (size_t)Bsz * (size_t)Hdim)
#define NC   128
#define NT   256
#define Mrows 65536            // B*T

// ---------------- static device scratch ----------------
__device__ float g_xproj[3ULL * 512ULL * 128ULL * 1024ULL]; // (gate, t, b, h)
__device__ float g_h[BH];                 // h fp32, [b][k]
__device__ float g_z[BH];                 // z gate fp32, [b][n]
__device__ uint32_t g_hbfu [2][BH / 2];   // h  bf16 hi/lo, [b][k/2] packed pairs
__device__ uint32_t g_rhbfu[2][BH / 2];   // r*h bf16 hi/lo
__device__ uint32_t g_xbf[2][(size_t)Mrows * (Din / 2)];   // x hi/lo packed pairs
__device__ uint32_t g_WzrF[2][256][64][32][2];  // rec B-frags [hl][ntile][k16][lane][reg]
__device__ uint32_t g_WhhF[2][128][64][32][2];
__device__ uint32_t g_WpF [2][384][8][32][8];   // proj B-frags [hl][ntile][kchunk][lane][kl*2+reg]
__device__ unsigned int g_bar = 0;

// ---------------- helpers ----------------
__device__ __forceinline__ float sigmoidf_(float x) { return 1.0f / (1.0f + __expf(-x)); }

__device__ __forceinline__ void bsplit(float v, __nv_bfloat16& hi, __nv_bfloat16& lo) {
    hi = __float2bfloat16(v);
    lo = __float2bfloat16(v - __bfloat162float(hi));
}
__device__ __forceinline__ uint32_t packbf(__nv_bfloat16 a, __nv_bfloat16 b) {
    unsigned short x = *(unsigned short*)&a, y = *(unsigned short*)&b;
    return (uint32_t)x | ((uint32_t)y << 16);
}

__device__ __forceinline__ void cp16(uint32_t s, const void* g) {
    asm volatile("cp.async.cg.shared.global [%0], [%1], 16;" :: "r"(s), "l"(g));
}
#define CP_COMMIT() asm volatile("cp.async.commit_group;")
#define CP_WAIT0()  asm volatile("cp.async.wait_group 0;")
#define CP_WAIT1()  asm volatile("cp.async.wait_group 1;")
#define CP_WAIT2()  asm volatile("cp.async.wait_group 2;")

__device__ __forceinline__ void grid_sync() {
    __syncthreads();
    if (threadIdx.x == 0) {
        __threadfence();
        unsigned int old = atomicAdd(&g_bar, 1u);
        unsigned int target = (old / NC + 1u) * NC;
        unsigned int v;
        do {
            asm volatile("ld.acquire.gpu.global.u32 %0, [%1];"
                         : "=r"(v) : "l"(&g_bar) : "memory");
        } while (v < target);
    }
    __syncthreads();
}

__device__ __forceinline__ void ldsm4(uint32_t (&r)[4], uint32_t a) {
    asm volatile("ldmatrix.sync.aligned.m8n8.x4.shared.b16 {%0,%1,%2,%3}, [%4];"
                 : "=r"(r[0]), "=r"(r[1]), "=r"(r[2]), "=r"(r[3]) : "r"(a));
}
__device__ __forceinline__ void mma16816(float (&d)[4], const uint32_t (&a)[4],
                                         uint32_t b0, uint32_t b1) {
    asm volatile(
        "mma.sync.aligned.m16n8k16.row.col.f32.bf16.bf16.f32 "
        "{%0,%1,%2,%3}, {%4,%5,%6,%7}, {%8,%9}, {%0,%1,%2,%3};"
        : "+f"(d[0]), "+f"(d[1]), "+f"(d[2]), "+f"(d[3])
        : "r"(a[0]), "r"(a[1]), "r"(a[2]), "r"(a[3]), "r"(b0), "r"(b1));
}

// ---------------- setup kernels ----------------
__global__ void init_h_kernel(const float* __restrict__ h0) {
    int i = blockIdx.x * 256 + threadIdx.x;        // BH/2
    int b = i >> 9, kp = i & 511;
    float2 v = *(const float2*)&h0[(size_t)b * Hdim + kp * 2];
    *(float2*)&g_h[(size_t)b * Hdim + kp * 2] = v;
    __nv_bfloat16 h0a, l0a, h1a, l1a;
    bsplit(v.x, h0a, l0a); bsplit(v.y, h1a, l1a);
    g_hbfu[0][(size_t)b * 512 + kp] = packbf(h0a, h1a);
    g_hbfu[1][(size_t)b * 512 + kp] = packbf(l0a, l1a);
}

__global__ void pack_x_kernel(const float* __restrict__ x) {
    size_t i = (size_t)blockIdx.x * 256 + threadIdx.x;   // Mrows*Din/2 = 16,777,216
    float2 v = *(const float2*)&x[i * 2];
    __nv_bfloat16 h0a, l0a, h1a, l1a;
    bsplit(v.x, h0a, l0a); bsplit(v.y, h1a, l1a);
    g_xbf[0][i] = packbf(h0a, h1a);
    g_xbf[1][i] = packbf(l0a, l1a);
}

__global__ void pack_WpF_kernel(const float* __restrict__ Wiu, const float* __restrict__ Wir,
                                const float* __restrict__ Wih) {
    int i = blockIdx.x * 256 + threadIdx.x;        // 384*8*32*8 = 786,432
    int e = i & 7, lane = (i >> 3) & 31, kc = (i >> 8) & 7, nt = i >> 11;
    int kl = e >> 1, reg = e & 1;
    int n = nt * 8 + (lane >> 2);
    int gate = n >> 10, nn = n & (Hdim - 1);
    const float* W = (gate == 0) ? Wiu : (gate == 1 ? Wir : Wih);
    int k = kc * 64 + kl * 16 + reg * 8 + (lane & 3) * 2;
    float v0 = W[(size_t)k * Hdim + nn];
    float v1 = W[(size_t)(k + 1) * Hdim + nn];
    __nv_bfloat16 h0a, l0a, h1a, l1a;
    bsplit(v0, h0a, l0a); bsplit(v1, h1a, l1a);
    g_WpF[0][nt][kc][lane][e] = packbf(h0a, h1a);
    g_WpF[1][nt][kc][lane][e] = packbf(l0a, l1a);
}

__global__ void pack_wzrF_kernel(const float* __restrict__ Whu, const float* __restrict__ Whr) {
    int i = blockIdx.x * 256 + threadIdx.x;        // 1,048,576
    int reg = i & 1, lane = (i >> 1) & 31, k16 = (i >> 6) & 63, nt = i >> 12;
    int n = nt * 8 + (lane >> 2);
    int k = k16 * 16 + reg * 8 + (lane & 3) * 2;
    const float* W = (n < Hdim) ? Whu : Whr;
    int nn = n & (Hdim - 1);
    float v0 = W[(size_t)k * Hdim + nn];
    float v1 = W[(size_t)(k + 1) * Hdim + nn];
    __nv_bfloat16 h0a, l0a, h1a, l1a;
    bsplit(v0, h0a, l0a); bsplit(v1, h1a, l1a);
    g_WzrF[0][nt][k16][lane][reg] = packbf(h0a, h1a);
    g_WzrF[1][nt][k16][lane][reg] = packbf(l0a, l1a);
}

__global__ void pack_whhF_kernel(const float* __restrict__ Whh) {
    int i = blockIdx.x * 256 + threadIdx.x;        // 524,288
    int reg = i & 1, lane = (i >> 1) & 31, k16 = (i >> 6) & 63, nt = i >> 12;
    int n = nt * 8 + (lane >> 2);
    int k = k16 * 16 + reg * 8 + (lane & 3) * 2;
    float v0 = Whh[(size_t)k * Hdim + n];
    float v1 = Whh[(size_t)(k + 1) * Hdim + n];
    __nv_bfloat16 h0a, l0a, h1a, l1a;
    bsplit(v0, h0a, l0a); bsplit(v1, h1a, l1a);
    g_WhhF[0][nt][k16][lane][reg] = packbf(h0a, h1a);
    g_WhhF[1][nt][k16][lane][reg] = packbf(l0a, l1a);
}

// ---------------- phase A: tensor-core proj  x(65536x512) @ W(512x3072) + bias ----------------
// grid (512, 24), 256 thr. CTA tile 128m x 128n. warp = (mw 0-3)x(nw 0-1): 32m x 64n.
// 3-stage cp.async pipeline, chunk k=64 (A chunk 32KB: 2 hl x 128 rows x 128B SW128).
#define PROJ_SMEM (3 * 32768)
__global__ void __launch_bounds__(256) proj_mma_kernel(
    const float* __restrict__ bu, const float* __restrict__ br, const float* __restrict__ bh)
{
    extern __shared__ char sm[];
    const uint32_t smb = (uint32_t)__cvta_generic_to_shared(sm);
    const int tid = threadIdx.x, wid = tid >> 5, lane = tid & 31;
    const int gid = lane >> 2, t4 = lane & 3;
    const int mw = wid & 3, nw = wid >> 2;
    const int rb = blockIdx.x * 128, cb = blockIdx.y * 128;
    const int gate = cb >> 10;
    const float* bias = (gate == 0) ? bu : (gate == 1 ? br : bh);

    const int lrowoff = ((lane >> 3) & 1) * 8 + (lane & 7);
    const int lkq = lane >> 4;
    const int lsw = (lane & 7) * 16;

    float acc[2][8][4];
#pragma unroll
    for (int mt = 0; mt < 2; mt++)
#pragma unroll
        for (int nt = 0; nt < 8; nt++)
#pragma unroll
            for (int i = 0; i < 4; i++) acc[mt][nt][i] = 0.f;

    auto load_chunk = [&](int st, int kc) {
#pragma unroll
        for (int q = 0; q < 8; q++) {
            int u = tid + q * 256;
            int hl = u >> 10, rem = u & 1023, row = rem >> 3, cu = rem & 7;
            uint32_t dst = smb + st * 32768 + hl * 16384 + row * 128
                         + ((cu * 16) ^ ((row & 7) * 16));
            cp16(dst, g_xbf[hl] + (size_t)(rb + row) * 256 + kc * 32 + cu * 4);
        }
        CP_COMMIT();
    };

    load_chunk(0, 0); load_chunk(1, 1); load_chunk(2, 2);
    for (int c = 0; c < 8; c++) {
        if (c <= 5)      CP_WAIT2();
        else if (c == 6) CP_WAIT1();
        else             CP_WAIT0();
        __syncthreads();
        const uint32_t base = smb + (c % 3) * 32768;
#pragma unroll
        for (int kl = 0; kl < 4; kl++) {
            const uint32_t bcol = (uint32_t)((kl * 32 + lkq * 16) ^ lsw);
            uint32_t Ah[2][4], Al[2][4];
#pragma unroll
            for (int mt = 0; mt < 2; mt++) {
                const int mtile = mw * 2 + mt;
                uint32_t ra = base + (uint32_t)((mtile * 16 + lrowoff) * 128) + bcol;
                ldsm4(Ah[mt], ra);
                ldsm4(Al[mt], ra + 16384);
            }
#pragma unroll
            for (int nt = 0; nt < 8; nt++) {
                const int ntile = blockIdx.y * 16 + nw * 8 + nt;
                unsigned long long bhp = *(const unsigned long long*)&g_WpF[0][ntile][c][lane][kl * 2];
                unsigned long long blp = *(const unsigned long long*)&g_WpF[1][ntile][c][lane][kl * 2];
                const uint32_t bh0 = (uint32_t)bhp, bh1 = (uint32_t)(bhp >> 32);
                const uint32_t bl0 = (uint32_t)blp, bl1 = (uint32_t)(blp >> 32);
#pragma unroll
                for (int mt = 0; mt < 2; mt++) {
                    mma16816(acc[mt][nt], Ah[mt], bh0, bh1);
                    mma16816(acc[mt][nt], Ah[mt], bl0, bl1);
                    mma16816(acc[mt][nt], Al[mt], bh0, bh1);
                }
            }
        }
        __syncthreads();
        if (c + 3 < 8) load_chunk(c % 3, c + 3);
    }

    // epilogue: add bias, scatter time-major (t = m & 511, b = m >> 9)
    float* gout = g_xproj + (size_t)gate * TBH;
#pragma unroll
    for (int nt = 0; nt < 8; nt++) {
        const int ncol = cb + nw * 64 + nt * 8 + t4 * 2;
        const int nn = ncol & (Hdim - 1);
        const float2 bv = *(const float2*)&bias[nn];
#pragma unroll
        for (int mt = 0; mt < 2; mt++) {
#pragma unroll
            for (int hf = 0; hf < 2; hf++) {
                const int m = rb + mw * 32 + mt * 16 + gid + hf * 8;
                const int t = m & (Tseq - 1), bb = m >> 9;
                float2 v;
                v.x = acc[mt][nt][hf * 2]     + bv.x;
                v.y = acc[mt][nt][hf * 2 + 1] + bv.y;
                *(float2*)&gout[((size_t)(t * Bsz + bb)) * Hdim + nn] = v;
            }
        }
    }
}

// ---------------- persistent recurrence (mma.sync bf16 3-pass, 3-stage pipeline) ----------------
#define REC_SMEM (3 * 16384)
__global__ void __launch_bounds__(NT, 1) gru_rec_kernel(float* __restrict__ out)
{
    extern __shared__ char sm[];
    const uint32_t smb = (uint32_t)__cvta_generic_to_shared(sm);

    const int tid  = threadIdx.x, cta = blockIdx.x;
    const int wid  = tid >> 5, lane = tid & 31;
    const int gid  = lane >> 2, t4 = lane & 3;
    const int bhalf = cta & 1, bbase = bhalf * 64;
    const int ngrp  = cta >> 1;            // 0..63
    const int isR   = ngrp >= 32;

    const int mg = wid & 1, nq = wid >> 1;
    const int ntile1 = ngrp * 4 + nq;
    const int mt2 = wid >> 1, nt2 = wid & 1;
    const int ntile2 = ngrp * 2 + nt2;

    const int lrowoff = ((lane >> 3) & 1) * 8 + (lane & 7);
    const int lkq  = lane >> 4;
    const int lsw  = (lane & 7) * 16;

    auto load_chunk = [&](int st, int k0, const uint32_t* s0, const uint32_t* s1) {
#pragma unroll
        for (int q = 0; q < 4; q++) {
            int u = tid + q * NT;
            int hl = u >> 9, rem = u & 511;
            int row = rem >> 3, cu = rem & 7;
            uint32_t dst = smb + st * 16384 + hl * 8192 + row * 128
                         + ((cu * 16) ^ ((row & 7) * 16));
            const uint32_t* s = (hl ? s1 : s0)
                              + (size_t)(bbase + row) * 512 + (k0 >> 1) + cu * 4;
            cp16(dst, s);
        }
        CP_COMMIT();
    };

    for (int t = 0; t < Tseq; t++) {
        // ================= phase 1 : z / r =================
        float acc[2][4];
#pragma unroll
        for (int m = 0; m < 2; m++)
#pragma unroll
            for (int i = 0; i < 4; i++) acc[m][i] = 0.f;

        load_chunk(0, 0, g_hbfu[0], g_hbfu[1]);
        load_chunk(1, 64, g_hbfu[0], g_hbfu[1]);
        load_chunk(2, 128, g_hbfu[0], g_hbfu[1]);
        for (int c = 0; c < 16; c++) {
            if (c <= 13)      CP_WAIT2();
            else if (c == 14) CP_WAIT1();
            else              CP_WAIT0();
            __syncthreads();
            unsigned long long Bh[4], Bl[4];
#pragma unroll
            for (int i = 0; i < 4; i++) {
                Bh[i] = *(const unsigned long long*)&g_WzrF[0][ntile1][c * 4 + i][lane][0];
                Bl[i] = *(const unsigned long long*)&g_WzrF[1][ntile1][c * 4 + i][lane][0];
            }
            const uint32_t base = smb + (c % 3) * 16384;
#pragma unroll
            for (int kl = 0; kl < 4; kl++) {
                const uint32_t bcol = (uint32_t)((kl * 32 + lkq * 16) ^ lsw);
                uint32_t Ah[2][4], Al[2][4];
#pragma unroll
                for (int mt = 0; mt < 2; mt++) {
                    const int mtile = mg * 2 + mt;
                    uint32_t ra = base + (uint32_t)((mtile * 16 + lrowoff) * 128) + bcol;
                    ldsm4(Ah[mt], ra);
                    ldsm4(Al[mt], ra + 8192);
                }
                const uint32_t bh0 = (uint32_t)Bh[kl], bh1 = (uint32_t)(Bh[kl] >> 32);
                const uint32_t bl0 = (uint32_t)Bl[kl], bl1 = (uint32_t)(Bl[kl] >> 32);
#pragma unroll
                for (int mt = 0; mt < 2; mt++) {
                    mma16816(acc[mt], Ah[mt], bh0, bh1);
                    mma16816(acc[mt], Ah[mt], bl0, bl1);
                    mma16816(acc[mt], Al[mt], bh0, bh1);
                }
            }
            __syncthreads();
            if (c + 3 < 16) load_chunk(c % 3, (c + 3) * 64, g_hbfu[0], g_hbfu[1]);
        }

        // phase1 epilogue
        {
            const float* xg = g_xproj + (isR ? TBH : (size_t)0) + (size_t)t * BH;
            const int Ncol = ngrp * 32 + nq * 8 + t4 * 2;
#pragma unroll
            for (int mt = 0; mt < 2; mt++) {
                const int mtile = mg * 2 + mt;
#pragma unroll
                for (int hf = 0; hf < 2; hf++) {
                    const int b = bbase + mtile * 16 + gid + hf * 8;
                    const float dx = acc[mt][hf * 2], dy = acc[mt][hf * 2 + 1];
                    if (!isR) {
                        float2 xu = __ldcs((const float2*)(xg + (size_t)b * Hdim + Ncol));
                        float2 zv;
                        zv.x = sigmoidf_(dx + xu.x);
                        zv.y = sigmoidf_(dy + xu.y);
                        *(float2*)&g_z[(size_t)b * Hdim + Ncol] = zv;
                    } else {
                        const int j = Ncol - Hdim;
                        float2 xr = __ldcs((const float2*)(xg + (size_t)b * Hdim + j));
                        float2 h2 = __ldcg((const float2*)&g_h[(size_t)b * Hdim + j]);
                        float r0 = sigmoidf_(dx + xr.x) * h2.x;
                        float r1 = sigmoidf_(dy + xr.y) * h2.y;
                        __nv_bfloat16 H0, L0, H1, L1;
                        bsplit(r0, H0, L0); bsplit(r1, H1, L1);
                        g_rhbfu[0][(size_t)b * 512 + (j >> 1)] = packbf(H0, H1);
                        g_rhbfu[1][(size_t)b * 512 + (j >> 1)] = packbf(L0, L1);
                    }
                }
            }
        }
        grid_sync();

        // ================= phase 2 : candidate + update =================
        float ac2[4] = { 0.f, 0.f, 0.f, 0.f };
        load_chunk(0, 0, g_rhbfu[0], g_rhbfu[1]);
        load_chunk(1, 64, g_rhbfu[0], g_rhbfu[1]);
        load_chunk(2, 128, g_rhbfu[0], g_rhbfu[1]);
        for (int c = 0; c < 16; c++) {
            if (c <= 13)      CP_WAIT2();
            else if (c == 14) CP_WAIT1();
            else              CP_WAIT0();
            __syncthreads();
            unsigned long long Bh[4], Bl[4];
#pragma unroll
            for (int i = 0; i < 4; i++) {
                Bh[i] = *(const unsigned long long*)&g_WhhF[0][ntile2][c * 4 + i][lane][0];
                Bl[i] = *(const unsigned long long*)&g_WhhF[1][ntile2][c * 4 + i][lane][0];
            }
            const uint32_t base = smb + (c % 3) * 16384;
#pragma unroll
            for (int kl = 0; kl < 4; kl++) {
                const uint32_t bcol = (uint32_t)((kl * 32 + lkq * 16) ^ lsw);
                uint32_t Ah[4], Al[4];
                uint32_t ra = base + (uint32_t)((mt2 * 16 + lrowoff) * 128) + bcol;
                ldsm4(Ah, ra);
                ldsm4(Al, ra + 8192);
                const uint32_t bh0 = (uint32_t)Bh[kl], bh1 = (uint32_t)(Bh[kl] >> 32);
                const uint32_t bl0 = (uint32_t)Bl[kl], bl1 = (uint32_t)(Bl[kl] >> 32);
                mma16816(ac2, Ah, bh0, bh1);
                mma16816(ac2, Ah, bl0, bl1);
                mma16816(ac2, Al, bh0, bh1);
            }
            __syncthreads();
            if (c + 3 < 16) load_chunk(c % 3, (c + 3) * 64, g_rhbfu[0], g_rhbfu[1]);
        }

        // phase2 epilogue
        {
            const float* xh = g_xproj + 2 * TBH + (size_t)t * BH;
            const int n = ngrp * 16 + nt2 * 8 + t4 * 2;
#pragma unroll
            for (int hf = 0; hf < 2; hf++) {
                const int b = bbase + mt2 * 16 + gid + hf * 8;
                float2 xv = __ldcs((const float2*)(xh + (size_t)b * Hdim + n));
                float2 zv = __ldcg((const float2*)&g_z[(size_t)b * Hdim + n]);
                float2 hv = __ldcg((const float2*)&g_h[(size_t)b * Hdim + n]);
                float c0 = tanhf(ac2[hf * 2]     + xv.x);
                float c1 = tanhf(ac2[hf * 2 + 1] + xv.y);
                float hn0 = hv.x + zv.x * (c0 - hv.x);
                float hn1 = hv.y + zv.y * (c1 - hv.y);
                *(float2*)&g_h[(size_t)b * Hdim + n] = make_float2(hn0, hn1);
                __nv_bfloat16 H0, L0, H1, L1;
                bsplit(hn0, H0, L0); bsplit(hn1, H1, L1);
                g_hbfu[0][(size_t)b * 512 + (n >> 1)] = packbf(H0, H1);
                g_hbfu[1][(size_t)b * 512 + (n >> 1)] = packbf(L0, L1);
                if (out)
                    *(float2*)&out[(size_t)t * BH + (size_t)b * Hdim + n] = make_float2(hn0, hn1);
            }
        }
        grid_sync();
    }
}

// ---------------- final hidden state ----------------
__global__ void hlast_kernel(float* __restrict__ dst) {
    int i = blockIdx.x * 256 + threadIdx.x;
    dst[i] = g_h[i];
}

// ---------------- launch ----------------
extern "C" void kernel_launch(void* const* d_in, const int* in_sizes, int n_in,
                              void* d_out, int out_size)
{
    (void)in_sizes; (void)n_in;
    const float* x   = (const float*)d_in[0];
    const float* h0  = (const float*)d_in[1];
    const float* Wiu = (const float*)d_in[2];
    const float* Whu = (const float*)d_in[3];
    const float* bu  = (const float*)d_in[4];
    const float* Wir = (const float*)d_in[5];
    const float* Whr = (const float*)d_in[6];
    const float* br  = (const float*)d_in[7];
    const float* Wih = (const float*)d_in[8];
    const float* Whh = (const float*)d_in[9];
    const float* bh  = (const float*)d_in[10];
    float* out = (float*)d_out;

    const bool write_seq  = ((size_t)out_size >= TBH);
    const bool write_last = ((size_t)out_size >= TBH + (size_t)Bsz * Hdim);

    cudaFuncSetAttribute(proj_mma_kernel,
                         cudaFuncAttributeMaxDynamicSharedMemorySize, PROJ_SMEM);
    cudaFuncSetAttribute(gru_rec_kernel,
                         cudaFuncAttributeMaxDynamicSharedMemorySize, REC_SMEM);

    init_h_kernel<<<BH / 512, 256>>>(h0);
    pack_x_kernel<<<65536, 256>>>(x);
    pack_WpF_kernel<<<3072, 256>>>(Wiu, Wir, Wih);
    pack_wzrF_kernel<<<4096, 256>>>(Whu, Whr);
    pack_whhF_kernel<<<2048, 256>>>(Whh);

    dim3 pg(Mrows / 128, 3072 / 128);   // 512 x 24
    proj_mma_kernel<<<pg, 256, PROJ_SMEM>>>(bu, br, bh);

    gru_rec_kernel<<<NC, NT, REC_SMEM>>>(write_seq ? out : nullptr);

    if (write_last)        hlast_kernel<<<BH / 256, 256>>>(out + TBH);
    else if (!write_seq)   hlast_kernel<<<BH / 256, 256>>>(out);
}

// round 8
// speedup vs baseline: 4.5236x; 1.5008x over previous
#include <cuda_runtime.h>
#include <cuda_bf16.h>
#include <cstdint>

#define Bsz  128
#define Tseq 512
#define Din  512
#define Hdim 1024
#define BH   (Bsz * Hdim)
#define TBH  ((size_t)Tseq * (size_t)Bsz * (size_t)Hdim)
#define NC   128
#define NT   256
#define Mrows 65536            // B*T

// ---------------- static device scratch ----------------
__device__ float g_xproj[3ULL * 512ULL * 128ULL * 1024ULL]; // (gate, t, b, h)
__device__ float g_h[BH];                 // h fp32, [b][k]
__device__ float g_z[BH];                 // z gate fp32, [b][n]
__device__ uint32_t g_hbfu [2][BH / 2];   // h  bf16 hi/lo, [b][k/2] packed pairs
__device__ uint32_t g_rhbfu[2][BH / 2];   // r*h bf16 hi/lo
__device__ uint32_t g_xbf[2][(size_t)Mrows * (Din / 2)];   // x hi/lo packed pairs
__device__ uint32_t g_WzrC[256][64][32][4];     // rec B-frags combined [ntile][k16][lane][hi0,hi1,lo0,lo1]
__device__ uint32_t g_WhhC[128][64][32][4];
__device__ uint32_t g_WpF [2][384][8][32][8];   // proj B-frags [hl][ntile][kchunk][lane][kl*2+reg]
__device__ unsigned int g_bar = 0;

// ---------------- helpers ----------------
__device__ __forceinline__ float sigmoidf_(float x) { return 1.0f / (1.0f + __expf(-x)); }

__device__ __forceinline__ void bsplit(float v, __nv_bfloat16& hi, __nv_bfloat16& lo) {
    hi = __float2bfloat16(v);
    lo = __float2bfloat16(v - __bfloat162float(hi));
}
__device__ __forceinline__ uint32_t packbf(__nv_bfloat16 a, __nv_bfloat16 b) {
    unsigned short x = *(unsigned short*)&a, y = *(unsigned short*)&b;
    return (uint32_t)x | ((uint32_t)y << 16);
}

__device__ __forceinline__ void cp16(uint32_t s, const void* g) {
    asm volatile("cp.async.cg.shared.global [%0], [%1], 16;" :: "r"(s), "l"(g));
}
#define CP_COMMIT() asm volatile("cp.async.commit_group;")
#define CP_WAIT0()  asm volatile("cp.async.wait_group 0;")
#define CP_WAIT1()  asm volatile("cp.async.wait_group 1;")
#define CP_WAIT2()  asm volatile("cp.async.wait_group 2;")

__device__ __forceinline__ void grid_sync() {
    __syncthreads();
    if (threadIdx.x == 0) {
        __threadfence();
        unsigned int old = atomicAdd(&g_bar, 1u);
        unsigned int target = (old / NC + 1u) * NC;
        unsigned int v;
        do {
            asm volatile("ld.acquire.gpu.global.u32 %0, [%1];"
                         : "=r"(v) : "l"(&g_bar) : "memory");
        } while (v < target);
    }
    __syncthreads();
}

__device__ __forceinline__ void ldsm4(uint32_t (&r)[4], uint32_t a) {
    asm volatile("ldmatrix.sync.aligned.m8n8.x4.shared.b16 {%0,%1,%2,%3}, [%4];"
                 : "=r"(r[0]), "=r"(r[1]), "=r"(r[2]), "=r"(r[3]) : "r"(a));
}
__device__ __forceinline__ void mma16816(float (&d)[4], const uint32_t (&a)[4],
                                         uint32_t b0, uint32_t b1) {
    asm volatile(
        "mma.sync.aligned.m16n8k16.row.col.f32.bf16.bf16.f32 "
        "{%0,%1,%2,%3}, {%4,%5,%6,%7}, {%8,%9}, {%0,%1,%2,%3};"
        : "+f"(d[0]), "+f"(d[1]), "+f"(d[2]), "+f"(d[3])
        : "r"(a[0]), "r"(a[1]), "r"(a[2]), "r"(a[3]), "r"(b0), "r"(b1));
}

// ---------------- setup kernels ----------------
__global__ void init_h_kernel(const float* __restrict__ h0) {
    int i = blockIdx.x * 256 + threadIdx.x;        // BH/2
    int b = i >> 9, kp = i & 511;
    float2 v = *(const float2*)&h0[(size_t)b * Hdim + kp * 2];
    *(float2*)&g_h[(size_t)b * Hdim + kp * 2] = v;
    __nv_bfloat16 h0a, l0a, h1a, l1a;
    bsplit(v.x, h0a, l0a); bsplit(v.y, h1a, l1a);
    g_hbfu[0][(size_t)b * 512 + kp] = packbf(h0a, h1a);
    g_hbfu[1][(size_t)b * 512 + kp] = packbf(l0a, l1a);
}

__global__ void pack_x_kernel(const float* __restrict__ x) {
    size_t i = (size_t)blockIdx.x * 256 + threadIdx.x;   // Mrows*Din/2
    float2 v = *(const float2*)&x[i * 2];
    __nv_bfloat16 h0a, l0a, h1a, l1a;
    bsplit(v.x, h0a, l0a); bsplit(v.y, h1a, l1a);
    g_xbf[0][i] = packbf(h0a, h1a);
    g_xbf[1][i] = packbf(l0a, l1a);
}

__global__ void pack_WpF_kernel(const float* __restrict__ Wiu, const float* __restrict__ Wir,
                                const float* __restrict__ Wih) {
    int i = blockIdx.x * 256 + threadIdx.x;        // 786,432
    int e = i & 7, lane = (i >> 3) & 31, kc = (i >> 8) & 7, nt = i >> 11;
    int kl = e >> 1, reg = e & 1;
    int n = nt * 8 + (lane >> 2);
    int gate = n >> 10, nn = n & (Hdim - 1);
    const float* W = (gate == 0) ? Wiu : (gate == 1 ? Wir : Wih);
    int k = kc * 64 + kl * 16 + reg * 8 + (lane & 3) * 2;
    float v0 = W[(size_t)k * Hdim + nn];
    float v1 = W[(size_t)(k + 1) * Hdim + nn];
    __nv_bfloat16 h0a, l0a, h1a, l1a;
    bsplit(v0, h0a, l0a); bsplit(v1, h1a, l1a);
    g_WpF[0][nt][kc][lane][e] = packbf(h0a, h1a);
    g_WpF[1][nt][kc][lane][e] = packbf(l0a, l1a);
}

__global__ void pack_wzrC_kernel(const float* __restrict__ Whu, const float* __restrict__ Whr) {
    int i = blockIdx.x * 256 + threadIdx.x;        // 1,048,576
    int reg = i & 1, lane = (i >> 1) & 31, k16 = (i >> 6) & 63, nt = i >> 12;
    int n = nt * 8 + (lane >> 2);
    int k = k16 * 16 + reg * 8 + (lane & 3) * 2;
    const float* W = (n < Hdim) ? Whu : Whr;
    int nn = n & (Hdim - 1);
    float v0 = W[(size_t)k * Hdim + nn];
    float v1 = W[(size_t)(k + 1) * Hdim + nn];
    __nv_bfloat16 h0a, l0a, h1a, l1a;
    bsplit(v0, h0a, l0a); bsplit(v1, h1a, l1a);
    g_WzrC[nt][k16][lane][reg]     = packbf(h0a, h1a);
    g_WzrC[nt][k16][lane][2 + reg] = packbf(l0a, l1a);
}

__global__ void pack_whhC_kernel(const float* __restrict__ Whh) {
    int i = blockIdx.x * 256 + threadIdx.x;        // 524,288
    int reg = i & 1, lane = (i >> 1) & 31, k16 = (i >> 6) & 63, nt = i >> 12;
    int n = nt * 8 + (lane >> 2);
    int k = k16 * 16 + reg * 8 + (lane & 3) * 2;
    float v0 = Whh[(size_t)k * Hdim + n];
    float v1 = Whh[(size_t)(k + 1) * Hdim + n];
    __nv_bfloat16 h0a, l0a, h1a, l1a;
    bsplit(v0, h0a, l0a); bsplit(v1, h1a, l1a);
    g_WhhC[nt][k16][lane][reg]     = packbf(h0a, h1a);
    g_WhhC[nt][k16][lane][2 + reg] = packbf(l0a, l1a);
}

// ---------------- phase A: tensor-core proj (unchanged from R7) ----------------
#define PROJ_SMEM (3 * 32768)
__global__ void __launch_bounds__(256) proj_mma_kernel(
    const float* __restrict__ bu, const float* __restrict__ br, const float* __restrict__ bh)
{
    extern __shared__ char sm[];
    const uint32_t smb = (uint32_t)__cvta_generic_to_shared(sm);
    const int tid = threadIdx.x, wid = tid >> 5, lane = tid & 31;
    const int gid = lane >> 2, t4 = lane & 3;
    const int mw = wid & 3, nw = wid >> 2;
    const int rb = blockIdx.x * 128, cb = blockIdx.y * 128;
    const int gate = cb >> 10;
    const float* bias = (gate == 0) ? bu : (gate == 1 ? br : bh);

    const int lrowoff = ((lane >> 3) & 1) * 8 + (lane & 7);
    const int lkq = lane >> 4;
    const int lsw = (lane & 7) * 16;

    float acc[2][8][4];
#pragma unroll
    for (int mt = 0; mt < 2; mt++)
#pragma unroll
        for (int nt = 0; nt < 8; nt++)
#pragma unroll
            for (int i = 0; i < 4; i++) acc[mt][nt][i] = 0.f;

    auto load_chunk = [&](int st, int kc) {
#pragma unroll
        for (int q = 0; q < 8; q++) {
            int u = tid + q * 256;
            int hl = u >> 10, rem = u & 1023, row = rem >> 3, cu = rem & 7;
            uint32_t dst = smb + st * 32768 + hl * 16384 + row * 128
                         + ((cu * 16) ^ ((row & 7) * 16));
            cp16(dst, g_xbf[hl] + (size_t)(rb + row) * 256 + kc * 32 + cu * 4);
        }
        CP_COMMIT();
    };

    load_chunk(0, 0); load_chunk(1, 1); load_chunk(2, 2);
    for (int c = 0; c < 8; c++) {
        if (c <= 5)      CP_WAIT2();
        else if (c == 6) CP_WAIT1();
        else             CP_WAIT0();
        __syncthreads();
        const uint32_t base = smb + (c % 3) * 32768;
#pragma unroll
        for (int kl = 0; kl < 4; kl++) {
            const uint32_t bcol = (uint32_t)((kl * 32 + lkq * 16) ^ lsw);
            uint32_t Ah[2][4], Al[2][4];
#pragma unroll
            for (int mt = 0; mt < 2; mt++) {
                const int mtile = mw * 2 + mt;
                uint32_t ra = base + (uint32_t)((mtile * 16 + lrowoff) * 128) + bcol;
                ldsm4(Ah[mt], ra);
                ldsm4(Al[mt], ra + 16384);
            }
#pragma unroll
            for (int nt = 0; nt < 8; nt++) {
                const int ntile = blockIdx.y * 16 + nw * 8 + nt;
                unsigned long long bhp = *(const unsigned long long*)&g_WpF[0][ntile][c][lane][kl * 2];
                unsigned long long blp = *(const unsigned long long*)&g_WpF[1][ntile][c][lane][kl * 2];
                const uint32_t bh0 = (uint32_t)bhp, bh1 = (uint32_t)(bhp >> 32);
                const uint32_t bl0 = (uint32_t)blp, bl1 = (uint32_t)(blp >> 32);
#pragma unroll
                for (int mt = 0; mt < 2; mt++) {
                    mma16816(acc[mt][nt], Ah[mt], bh0, bh1);
                    mma16816(acc[mt][nt], Ah[mt], bl0, bl1);
                    mma16816(acc[mt][nt], Al[mt], bh0, bh1);
                }
            }
        }
        __syncthreads();
        if (c + 3 < 8) load_chunk(c % 3, c + 3);
    }

    float* gout = g_xproj + (size_t)gate * TBH;
#pragma unroll
    for (int nt = 0; nt < 8; nt++) {
        const int ncol = cb + nw * 64 + nt * 8 + t4 * 2;
        const int nn = ncol & (Hdim - 1);
        const float2 bv = *(const float2*)&bias[nn];
#pragma unroll
        for (int mt = 0; mt < 2; mt++) {
#pragma unroll
            for (int hf = 0; hf < 2; hf++) {
                const int m = rb + mw * 32 + mt * 16 + gid + hf * 8;
                const int t = m & (Tseq - 1), bb = m >> 9;
                float2 v;
                v.x = acc[mt][nt][hf * 2]     + bv.x;
                v.y = acc[mt][nt][hf * 2 + 1] + bv.y;
                *(float2*)&gout[((size_t)(t * Bsz + bb)) * Hdim + nn] = v;
            }
        }
    }
}

// ---------------- persistent recurrence: smem-resident weights ----------------
// smem: [0,131072) Wzr frags (4 ntiles) | [131072,196608) Whh frags (2 ntiles)
//       [196608,229376) A stages 2 x 16 KB
#define REC_SMEM 229376
__global__ void __launch_bounds__(NT, 1) gru_rec_kernel(float* __restrict__ out)
{
    extern __shared__ char sm[];
    const uint32_t smb = (uint32_t)__cvta_generic_to_shared(sm);
    const uint32_t abase = smb + 196608;

    const int tid  = threadIdx.x, cta = blockIdx.x;
    const int wid  = tid >> 5, lane = tid & 31;
    const int gid  = lane >> 2, t4 = lane & 3;
    const int bhalf = cta & 1, bbase = bhalf * 64;
    const int ngrp  = cta >> 1;            // 0..63
    const int isR   = ngrp >= 32;

    const int mg = wid & 1, nq = wid >> 1;
    const int mt2 = wid >> 1, nt2 = wid & 1;

    const int lrowoff = ((lane >> 3) & 1) * 8 + (lane & 7);
    const int lkq  = lane >> 4;
    const int lsw  = (lane & 7) * 16;

    // ---- preload this CTA's weight fragments into smem (once) ----
    {
        const char* s1 = (const char*)g_WzrC + (size_t)(ngrp * 4) * 32768;
#pragma unroll
        for (int q = 0; q < 32; q++)
            cp16(smb + (uint32_t)(tid + q * NT) * 16, s1 + (size_t)(tid + q * NT) * 16);
        const char* s2 = (const char*)g_WhhC + (size_t)(ngrp * 2) * 32768;
#pragma unroll
        for (int q = 0; q < 16; q++)
            cp16(smb + 131072 + (uint32_t)(tid + q * NT) * 16, s2 + (size_t)(tid + q * NT) * 16);
        CP_COMMIT();
        CP_WAIT0();
        __syncthreads();
    }

    auto load_chunk = [&](int st, int k0, const uint32_t* s0, const uint32_t* s1) {
#pragma unroll
        for (int q = 0; q < 4; q++) {
            int u = tid + q * NT;
            int hl = u >> 9, rem = u & 511;
            int row = rem >> 3, cu = rem & 7;
            uint32_t dst = abase + st * 16384 + hl * 8192 + row * 128
                         + ((cu * 16) ^ ((row & 7) * 16));
            const uint32_t* s = (hl ? s1 : s0)
                              + (size_t)(bbase + row) * 512 + (k0 >> 1) + cu * 4;
            cp16(dst, s);
        }
        CP_COMMIT();
    };

    for (int t = 0; t < Tseq; t++) {
        // ================= phase 1 : z / r =================
        float acc[2][4];
#pragma unroll
        for (int m = 0; m < 2; m++)
#pragma unroll
            for (int i = 0; i < 4; i++) acc[m][i] = 0.f;

        load_chunk(0, 0, g_hbfu[0], g_hbfu[1]);
        load_chunk(1, 64, g_hbfu[0], g_hbfu[1]);

        // prefetch epilogue operands (latency hidden under chunk loop)
        const int Ncol = ngrp * 32 + nq * 8 + t4 * 2;
        const int jj = isR ? (Ncol - Hdim) : Ncol;
        const float* xg = g_xproj + (isR ? TBH : (size_t)0) + (size_t)t * BH;
        float2 pxg[2][2], ph2[2][2];
#pragma unroll
        for (int mt = 0; mt < 2; mt++)
#pragma unroll
            for (int hf = 0; hf < 2; hf++) {
                const int b = bbase + (mg * 2 + mt) * 16 + gid + hf * 8;
                pxg[mt][hf] = __ldcs((const float2*)(xg + (size_t)b * Hdim + jj));
                if (isR) ph2[mt][hf] = __ldcg((const float2*)&g_h[(size_t)b * Hdim + jj]);
            }

        for (int c = 0; c < 16; c++) {
            if (c < 15) CP_WAIT1(); else CP_WAIT0();
            __syncthreads();
            const uint32_t base = abase + (c & 1) * 16384;
#pragma unroll
            for (int kl = 0; kl < 4; kl++) {
                const uint32_t bcol = (uint32_t)((kl * 32 + lkq * 16) ^ lsw);
                uint32_t Ah[2][4], Al[2][4];
#pragma unroll
                for (int mt = 0; mt < 2; mt++) {
                    const int mtile = mg * 2 + mt;
                    uint32_t ra = base + (uint32_t)((mtile * 16 + lrowoff) * 128) + bcol;
                    ldsm4(Ah[mt], ra);
                    ldsm4(Al[mt], ra + 8192);
                }
                const uint4 Bv = *(const uint4*)(sm + ((size_t)(nq * 2048 + (c * 4 + kl) * 32 + lane)) * 16);
#pragma unroll
                for (int mt = 0; mt < 2; mt++) {
                    mma16816(acc[mt], Ah[mt], Bv.x, Bv.y);
                    mma16816(acc[mt], Ah[mt], Bv.z, Bv.w);
                    mma16816(acc[mt], Al[mt], Bv.x, Bv.y);
                }
            }
            __syncthreads();
            if (c + 2 < 16) load_chunk(c & 1, (c + 2) * 64, g_hbfu[0], g_hbfu[1]);
        }

        // phase1 epilogue
#pragma unroll
        for (int mt = 0; mt < 2; mt++) {
#pragma unroll
            for (int hf = 0; hf < 2; hf++) {
                const int b = bbase + (mg * 2 + mt) * 16 + gid + hf * 8;
                const float dx = acc[mt][hf * 2], dy = acc[mt][hf * 2 + 1];
                if (!isR) {
                    float2 zv;
                    zv.x = sigmoidf_(dx + pxg[mt][hf].x);
                    zv.y = sigmoidf_(dy + pxg[mt][hf].y);
                    *(float2*)&g_z[(size_t)b * Hdim + Ncol] = zv;
                } else {
                    float r0 = sigmoidf_(dx + pxg[mt][hf].x) * ph2[mt][hf].x;
                    float r1 = sigmoidf_(dy + pxg[mt][hf].y) * ph2[mt][hf].y;
                    __nv_bfloat16 H0, L0, H1, L1;
                    bsplit(r0, H0, L0); bsplit(r1, H1, L1);
                    g_rhbfu[0][(size_t)b * 512 + (jj >> 1)] = packbf(H0, H1);
                    g_rhbfu[1][(size_t)b * 512 + (jj >> 1)] = packbf(L0, L1);
                }
            }
        }
        grid_sync();

        // ================= phase 2 : candidate + update =================
        float ac2[4] = { 0.f, 0.f, 0.f, 0.f };
        load_chunk(0, 0, g_rhbfu[0], g_rhbfu[1]);
        load_chunk(1, 64, g_rhbfu[0], g_rhbfu[1]);

        const int n = ngrp * 16 + nt2 * 8 + t4 * 2;
        const float* xh = g_xproj + 2 * TBH + (size_t)t * BH;
        float2 pxh[2], pz2[2], phv[2];
#pragma unroll
        for (int hf = 0; hf < 2; hf++) {
            const int b = bbase + mt2 * 16 + gid + hf * 8;
            pxh[hf] = __ldcs((const float2*)(xh + (size_t)b * Hdim + n));
            pz2[hf] = __ldcg((const float2*)&g_z[(size_t)b * Hdim + n]);
            phv[hf] = __ldcg((const float2*)&g_h[(size_t)b * Hdim + n]);
        }

        for (int c = 0; c < 16; c++) {
            if (c < 15) CP_WAIT1(); else CP_WAIT0();
            __syncthreads();
            const uint32_t base = abase + (c & 1) * 16384;
#pragma unroll
            for (int kl = 0; kl < 4; kl++) {
                const uint32_t bcol = (uint32_t)((kl * 32 + lkq * 16) ^ lsw);
                uint32_t Ah[4], Al[4];
                uint32_t ra = base + (uint32_t)((mt2 * 16 + lrowoff) * 128) + bcol;
                ldsm4(Ah, ra);
                ldsm4(Al, ra + 8192);
                const uint4 Bv = *(const uint4*)(sm + 131072
                               + ((size_t)(nt2 * 2048 + (c * 4 + kl) * 32 + lane)) * 16);
                mma16816(ac2, Ah, Bv.x, Bv.y);
                mma16816(ac2, Ah, Bv.z, Bv.w);
                mma16816(ac2, Al, Bv.x, Bv.y);
            }
            __syncthreads();
            if (c + 2 < 16) load_chunk(c & 1, (c + 2) * 64, g_rhbfu[0], g_rhbfu[1]);
        }

        // phase2 epilogue
#pragma unroll
        for (int hf = 0; hf < 2; hf++) {
            const int b = bbase + mt2 * 16 + gid + hf * 8;
            float c0 = tanhf(ac2[hf * 2]     + pxh[hf].x);
            float c1 = tanhf(ac2[hf * 2 + 1] + pxh[hf].y);
            float hn0 = phv[hf].x + pz2[hf].x * (c0 - phv[hf].x);
            float hn1 = phv[hf].y + pz2[hf].y * (c1 - phv[hf].y);
            *(float2*)&g_h[(size_t)b * Hdim + n] = make_float2(hn0, hn1);
            __nv_bfloat16 H0, L0, H1, L1;
            bsplit(hn0, H0, L0); bsplit(hn1, H1, L1);
            g_hbfu[0][(size_t)b * 512 + (n >> 1)] = packbf(H0, H1);
            g_hbfu[1][(size_t)b * 512 + (n >> 1)] = packbf(L0, L1);
            if (out)
                *(float2*)&out[(size_t)t * BH + (size_t)b * Hdim + n] = make_float2(hn0, hn1);
        }
        grid_sync();
    }
}

// ---------------- final hidden state ----------------
__global__ void hlast_kernel(float* __restrict__ dst) {
    int i = blockIdx.x * 256 + threadIdx.x;
    dst[i] = g_h[i];
}

// ---------------- launch ----------------
extern "C" void kernel_launch(void* const* d_in, const int* in_sizes, int n_in,
                              void* d_out, int out_size)
{
    (void)in_sizes; (void)n_in;
    const float* x   = (const float*)d_in[0];
    const float* h0  = (const float*)d_in[1];
    const float* Wiu = (const float*)d_in[2];
    const float* Whu = (const float*)d_in[3];
    const float* bu  = (const float*)d_in[4];
    const float* Wir = (const float*)d_in[5];
    const float* Whr = (const float*)d_in[6];
    const float* br  = (const float*)d_in[7];
    const float* Wih = (const float*)d_in[8];
    const float* Whh = (const float*)d_in[9];
    const float* bh  = (const float*)d_in[10];
    float* out = (float*)d_out;

    const bool write_seq  = ((size_t)out_size >= TBH);
    const bool write_last = ((size_t)out_size >= TBH + (size_t)Bsz * Hdim);

    cudaFuncSetAttribute(proj_mma_kernel,
                         cudaFuncAttributeMaxDynamicSharedMemorySize, PROJ_SMEM);
    cudaFuncSetAttribute(gru_rec_kernel,
                         cudaFuncAttributeMaxDynamicSharedMemorySize, REC_SMEM);

    init_h_kernel<<<BH / 512, 256>>>(h0);
    pack_x_kernel<<<65536, 256>>>(x);
    pack_WpF_kernel<<<3072, 256>>>(Wiu, Wir, Wih);
    pack_wzrC_kernel<<<4096, 256>>>(Whu, Whr);
    pack_whhC_kernel<<<2048, 256>>>(Whh);

    dim3 pg(Mrows / 128, 3072 / 128);   // 512 x 24
    proj_mma_kernel<<<pg, 256, PROJ_SMEM>>>(bu, br, bh);

    gru_rec_kernel<<<NC, NT, REC_SMEM>>>(write_seq ? out : nullptr);

    if (write_last)        hlast_kernel<<<BH / 256, 256>>>(out + TBH);
    else if (!write_seq)   hlast_kernel<<<BH / 256, 256>>>(out);
}

// round 9
// speedup vs baseline: 5.5845x; 1.2345x over previous
#include <cuda_runtime.h>
#include <cuda_bf16.h>
#include <cuda_fp16.h>
#include <cstdint>

#define Bsz  128
#define Tseq 512
#define Din  512
#define Hdim 1024
#define BH   (Bsz * Hdim)
#define TBH  ((size_t)Tseq * (size_t)Bsz * (size_t)Hdim)
#define NC   128
#define NT   256
#define Mrows 65536            // B*T

// ---------------- static device scratch ----------------
__device__ float g_xproj[3ULL * 512ULL * 128ULL * 1024ULL]; // (gate, t, b, h)
__device__ float g_h[BH];                 // h fp32, [b][k]
__device__ float g_z[BH];                 // z gate fp32, [b][n]
__device__ uint32_t g_hfp [BH / 2];       // h  fp16 packed pairs [b][k/2]
__device__ uint32_t g_rhfp[BH / 2];       // r*h fp16 packed pairs
__device__ uint32_t g_xbf[2][(size_t)Mrows * (Din / 2)];   // x bf16 hi/lo (proj)
__device__ uint32_t g_WzrC[256][64][32][4];     // rec B-frags fp16 [ntile][k16][lane][hi0,hi1,lo0,lo1]
__device__ uint32_t g_WhhC[128][64][32][4];
__device__ uint32_t g_WpF [2][384][8][32][8];   // proj B-frags bf16
__device__ unsigned int g_bar = 0;

// ---------------- helpers ----------------
__device__ __forceinline__ float sigmoidf_(float x) { return 1.0f / (1.0f + __expf(-x)); }

__device__ __forceinline__ void bsplit(float v, __nv_bfloat16& hi, __nv_bfloat16& lo) {
    hi = __float2bfloat16(v);
    lo = __float2bfloat16(v - __bfloat162float(hi));
}
__device__ __forceinline__ uint32_t packbf(__nv_bfloat16 a, __nv_bfloat16 b) {
    unsigned short x = *(unsigned short*)&a, y = *(unsigned short*)&b;
    return (uint32_t)x | ((uint32_t)y << 16);
}
__device__ __forceinline__ void hsplit(float v, __half& hi, __half& lo) {
    hi = __float2half_rn(v);
    lo = __float2half_rn(v - __half2float(hi));
}
__device__ __forceinline__ uint32_t packh(__half a, __half b) {
    __half2 h2 = __halves2half2(a, b);
    return *(uint32_t*)&h2;
}

__device__ __forceinline__ void cp16(uint32_t s, const void* g) {
    asm volatile("cp.async.cg.shared.global [%0], [%1], 16;" :: "r"(s), "l"(g));
}
#define CP_COMMIT() asm volatile("cp.async.commit_group;")
#define CP_WAIT0()  asm volatile("cp.async.wait_group 0;")
#define CP_WAIT1()  asm volatile("cp.async.wait_group 1;")
#define CP_WAIT2()  asm volatile("cp.async.wait_group 2;")

__device__ __forceinline__ void grid_sync() {
    __syncthreads();
    if (threadIdx.x == 0) {
        __threadfence();
        unsigned int old = atomicAdd(&g_bar, 1u);
        unsigned int target = (old / NC + 1u) * NC;
        unsigned int v;
        do {
            asm volatile("ld.acquire.gpu.global.u32 %0, [%1];"
                         : "=r"(v) : "l"(&g_bar) : "memory");
        } while (v < target);
    }
    __syncthreads();
}

__device__ __forceinline__ void ldsm4(uint32_t (&r)[4], uint32_t a) {
    asm volatile("ldmatrix.sync.aligned.m8n8.x4.shared.b16 {%0,%1,%2,%3}, [%4];"
                 : "=r"(r[0]), "=r"(r[1]), "=r"(r[2]), "=r"(r[3]) : "r"(a));
}
__device__ __forceinline__ void mma_bf(float (&d)[4], const uint32_t (&a)[4],
                                       uint32_t b0, uint32_t b1) {
    asm volatile(
        "mma.sync.aligned.m16n8k16.row.col.f32.bf16.bf16.f32 "
        "{%0,%1,%2,%3}, {%4,%5,%6,%7}, {%8,%9}, {%0,%1,%2,%3};"
        : "+f"(d[0]), "+f"(d[1]), "+f"(d[2]), "+f"(d[3])
        : "r"(a[0]), "r"(a[1]), "r"(a[2]), "r"(a[3]), "r"(b0), "r"(b1));
}
__device__ __forceinline__ void mma_hf(float (&d)[4], const uint32_t (&a)[4],
                                       uint32_t b0, uint32_t b1) {
    asm volatile(
        "mma.sync.aligned.m16n8k16.row.col.f32.f16.f16.f32 "
        "{%0,%1,%2,%3}, {%4,%5,%6,%7}, {%8,%9}, {%0,%1,%2,%3};"
        : "+f"(d[0]), "+f"(d[1]), "+f"(d[2]), "+f"(d[3])
        : "r"(a[0]), "r"(a[1]), "r"(a[2]), "r"(a[3]), "r"(b0), "r"(b1));
}

// ---------------- setup kernels ----------------
__global__ void init_h_kernel(const float* __restrict__ h0) {
    int i = blockIdx.x * 256 + threadIdx.x;        // BH/2
    int b = i >> 9, kp = i & 511;
    float2 v = *(const float2*)&h0[(size_t)b * Hdim + kp * 2];
    *(float2*)&g_h[(size_t)b * Hdim + kp * 2] = v;
    g_hfp[(size_t)b * 512 + kp] = packh(__float2half_rn(v.x), __float2half_rn(v.y));
}

__global__ void pack_x_kernel(const float* __restrict__ x) {
    size_t i = (size_t)blockIdx.x * 256 + threadIdx.x;   // Mrows*Din/2
    float2 v = *(const float2*)&x[i * 2];
    __nv_bfloat16 h0a, l0a, h1a, l1a;
    bsplit(v.x, h0a, l0a); bsplit(v.y, h1a, l1a);
    g_xbf[0][i] = packbf(h0a, h1a);
    g_xbf[1][i] = packbf(l0a, l1a);
}

__global__ void pack_WpF_kernel(const float* __restrict__ Wiu, const float* __restrict__ Wir,
                                const float* __restrict__ Wih) {
    int i = blockIdx.x * 256 + threadIdx.x;        // 786,432
    int e = i & 7, lane = (i >> 3) & 31, kc = (i >> 8) & 7, nt = i >> 11;
    int kl = e >> 1, reg = e & 1;
    int n = nt * 8 + (lane >> 2);
    int gate = n >> 10, nn = n & (Hdim - 1);
    const float* W = (gate == 0) ? Wiu : (gate == 1 ? Wir : Wih);
    int k = kc * 64 + kl * 16 + reg * 8 + (lane & 3) * 2;
    float v0 = W[(size_t)k * Hdim + nn];
    float v1 = W[(size_t)(k + 1) * Hdim + nn];
    __nv_bfloat16 h0a, l0a, h1a, l1a;
    bsplit(v0, h0a, l0a); bsplit(v1, h1a, l1a);
    g_WpF[0][nt][kc][lane][e] = packbf(h0a, h1a);
    g_WpF[1][nt][kc][lane][e] = packbf(l0a, l1a);
}

__global__ void pack_wzrC_kernel(const float* __restrict__ Whu, const float* __restrict__ Whr) {
    int i = blockIdx.x * 256 + threadIdx.x;        // 1,048,576
    int reg = i & 1, lane = (i >> 1) & 31, k16 = (i >> 6) & 63, nt = i >> 12;
    int n = nt * 8 + (lane >> 2);
    int k = k16 * 16 + reg * 8 + (lane & 3) * 2;
    const float* W = (n < Hdim) ? Whu : Whr;
    int nn = n & (Hdim - 1);
    float v0 = W[(size_t)k * Hdim + nn];
    float v1 = W[(size_t)(k + 1) * Hdim + nn];
    __half h0a, l0a, h1a, l1a;
    hsplit(v0, h0a, l0a); hsplit(v1, h1a, l1a);
    g_WzrC[nt][k16][lane][reg]     = packh(h0a, h1a);
    g_WzrC[nt][k16][lane][2 + reg] = packh(l0a, l1a);
}

__global__ void pack_whhC_kernel(const float* __restrict__ Whh) {
    int i = blockIdx.x * 256 + threadIdx.x;        // 524,288
    int reg = i & 1, lane = (i >> 1) & 31, k16 = (i >> 6) & 63, nt = i >> 12;
    int n = nt * 8 + (lane >> 2);
    int k = k16 * 16 + reg * 8 + (lane & 3) * 2;
    float v0 = Whh[(size_t)k * Hdim + n];
    float v1 = Whh[(size_t)(k + 1) * Hdim + n];
    __half h0a, l0a, h1a, l1a;
    hsplit(v0, h0a, l0a); hsplit(v1, h1a, l1a);
    g_WhhC[nt][k16][lane][reg]     = packh(h0a, h1a);
    g_WhhC[nt][k16][lane][2 + reg] = packh(l0a, l1a);
}

// ---------------- phase A: tensor-core proj (bf16 3-pass, unchanged) ----------------
#define PROJ_SMEM (3 * 32768)
__global__ void __launch_bounds__(256) proj_mma_kernel(
    const float* __restrict__ bu, const float* __restrict__ br, const float* __restrict__ bh)
{
    extern __shared__ char sm[];
    const uint32_t smb = (uint32_t)__cvta_generic_to_shared(sm);
    const int tid = threadIdx.x, wid = tid >> 5, lane = tid & 31;
    const int gid = lane >> 2, t4 = lane & 3;
    const int mw = wid & 3, nw = wid >> 2;
    const int rb = blockIdx.x * 128, cb = blockIdx.y * 128;
    const int gate = cb >> 10;
    const float* bias = (gate == 0) ? bu : (gate == 1 ? br : bh);

    const int lrowoff = ((lane >> 3) & 1) * 8 + (lane & 7);
    const int lkq = lane >> 4;
    const int lsw = (lane & 7) * 16;

    float acc[2][8][4];
#pragma unroll
    for (int mt = 0; mt < 2; mt++)
#pragma unroll
        for (int nt = 0; nt < 8; nt++)
#pragma unroll
            for (int i = 0; i < 4; i++) acc[mt][nt][i] = 0.f;

    auto load_chunk = [&](int st, int kc) {
#pragma unroll
        for (int q = 0; q < 8; q++) {
            int u = tid + q * 256;
            int hl = u >> 10, rem = u & 1023, row = rem >> 3, cu = rem & 7;
            uint32_t dst = smb + st * 32768 + hl * 16384 + row * 128
                         + ((cu * 16) ^ ((row & 7) * 16));
            cp16(dst, g_xbf[hl] + (size_t)(rb + row) * 256 + kc * 32 + cu * 4);
        }
        CP_COMMIT();
    };

    load_chunk(0, 0); load_chunk(1, 1); load_chunk(2, 2);
    for (int c = 0; c < 8; c++) {
        if (c <= 5)      CP_WAIT2();
        else if (c == 6) CP_WAIT1();
        else             CP_WAIT0();
        __syncthreads();
        const uint32_t base = smb + (c % 3) * 32768;
#pragma unroll
        for (int kl = 0; kl < 4; kl++) {
            const uint32_t bcol = (uint32_t)((kl * 32 + lkq * 16) ^ lsw);
            uint32_t Ah[2][4], Al[2][4];
#pragma unroll
            for (int mt = 0; mt < 2; mt++) {
                const int mtile = mw * 2 + mt;
                uint32_t ra = base + (uint32_t)((mtile * 16 + lrowoff) * 128) + bcol;
                ldsm4(Ah[mt], ra);
                ldsm4(Al[mt], ra + 16384);
            }
#pragma unroll
            for (int nt = 0; nt < 8; nt++) {
                const int ntile = blockIdx.y * 16 + nw * 8 + nt;
                unsigned long long bhp = *(const unsigned long long*)&g_WpF[0][ntile][c][lane][kl * 2];
                unsigned long long blp = *(const unsigned long long*)&g_WpF[1][ntile][c][lane][kl * 2];
                const uint32_t bh0 = (uint32_t)bhp, bh1 = (uint32_t)(bhp >> 32);
                const uint32_t bl0 = (uint32_t)blp, bl1 = (uint32_t)(blp >> 32);
#pragma unroll
                for (int mt = 0; mt < 2; mt++) {
                    mma_bf(acc[mt][nt], Ah[mt], bh0, bh1);
                    mma_bf(acc[mt][nt], Ah[mt], bl0, bl1);
                    mma_bf(acc[mt][nt], Al[mt], bh0, bh1);
                }
            }
        }
        __syncthreads();
        if (c + 3 < 8) load_chunk(c % 3, c + 3);
    }

    float* gout = g_xproj + (size_t)gate * TBH;
#pragma unroll
    for (int nt = 0; nt < 8; nt++) {
        const int ncol = cb + nw * 64 + nt * 8 + t4 * 2;
        const int nn = ncol & (Hdim - 1);
        const float2 bv = *(const float2*)&bias[nn];
#pragma unroll
        for (int mt = 0; mt < 2; mt++) {
#pragma unroll
            for (int hf = 0; hf < 2; hf++) {
                const int m = rb + mw * 32 + mt * 16 + gid + hf * 8;
                const int t = m & (Tseq - 1), bb = m >> 9;
                float2 v;
                v.x = acc[mt][nt][hf * 2]     + bv.x;
                v.y = acc[mt][nt][hf * 2 + 1] + bv.y;
                *(float2*)&gout[((size_t)(t * Bsz + bb)) * Hdim + nn] = v;
            }
        }
    }
}

// ---------------- persistent recurrence: fp16 A-single / B hi+lo, 2-pass ----------------
// smem: [0,131072) Wzr frags (4 ntiles) | [131072,196608) Whh frags (2 ntiles)
//       [196608, 212992) A stages 2 x 8 KB
#define REC_SMEM 212992
__global__ void __launch_bounds__(NT, 1) gru_rec_kernel(float* __restrict__ out)
{
    extern __shared__ char sm[];
    const uint32_t smb = (uint32_t)__cvta_generic_to_shared(sm);
    const uint32_t abase = smb + 196608;

    const int tid  = threadIdx.x, cta = blockIdx.x;
    const int wid  = tid >> 5, lane = tid & 31;
    const int gid  = lane >> 2, t4 = lane & 3;
    const int bhalf = cta & 1, bbase = bhalf * 64;
    const int ngrp  = cta >> 1;            // 0..63
    const int isR   = ngrp >= 32;

    // warp tiling: phase1 = 4 mtiles x 2 n-halves(16 cols); phase2 = 4 mtiles x 2 ntiles(8 cols)
    const int mw = wid & 3, nh = wid >> 2;

    const int lrowoff = ((lane >> 3) & 1) * 8 + (lane & 7);
    const int lkq  = lane >> 4;
    const int lsw  = (lane & 7) * 16;

    // ---- preload this CTA's weight fragments into smem (once) ----
    {
        const char* s1 = (const char*)g_WzrC + (size_t)(ngrp * 4) * 32768;
#pragma unroll
        for (int q = 0; q < 32; q++)
            cp16(smb + (uint32_t)(tid + q * NT) * 16, s1 + (size_t)(tid + q * NT) * 16);
        const char* s2 = (const char*)g_WhhC + (size_t)(ngrp * 2) * 32768;
#pragma unroll
        for (int q = 0; q < 16; q++)
            cp16(smb + 131072 + (uint32_t)(tid + q * NT) * 16, s2 + (size_t)(tid + q * NT) * 16);
        CP_COMMIT();
        CP_WAIT0();
        __syncthreads();
    }

    // A chunk: 64 rows x 64 k fp16 = 8 KB per stage
    auto load_chunk = [&](int st, int k0, const uint32_t* s) {
#pragma unroll
        for (int q = 0; q < 2; q++) {
            int u = tid + q * NT;            // 0..511
            int row = u >> 3, cu = u & 7;
            uint32_t dst = abase + st * 8192 + row * 128
                         + ((cu * 16) ^ ((row & 7) * 16));
            cp16(dst, s + (size_t)(bbase + row) * 512 + (k0 >> 1) + cu * 4);
        }
        CP_COMMIT();
    };

    for (int t = 0; t < Tseq; t++) {
        // ================= phase 1 : z / r =================
        float acc[2][4];
#pragma unroll
        for (int nt = 0; nt < 2; nt++)
#pragma unroll
            for (int i = 0; i < 4; i++) acc[nt][i] = 0.f;

        load_chunk(0, 0, g_hfp);
        load_chunk(1, 64, g_hfp);

        // prefetch epilogue operands
        const int Ncol0 = ngrp * 32 + nh * 16 + t4 * 2;     // + nt*8
        const int jj0 = isR ? (Ncol0 - Hdim) : Ncol0;
        const float* xg = g_xproj + (isR ? TBH : (size_t)0) + (size_t)t * BH;
        float2 pxg[2][2], ph2[2][2];
#pragma unroll
        for (int nt = 0; nt < 2; nt++)
#pragma unroll
            for (int hf = 0; hf < 2; hf++) {
                const int b = bbase + mw * 16 + gid + hf * 8;
                pxg[nt][hf] = __ldcs((const float2*)(xg + (size_t)b * Hdim + jj0 + nt * 8));
                if (isR) ph2[nt][hf] = __ldcg((const float2*)&g_h[(size_t)b * Hdim + jj0 + nt * 8]);
            }

        for (int c = 0; c < 16; c++) {
            if (c < 15) CP_WAIT1(); else CP_WAIT0();
            __syncthreads();
            const uint32_t base = abase + (c & 1) * 8192;
#pragma unroll
            for (int kl = 0; kl < 4; kl++) {
                const uint32_t bcol = (uint32_t)((kl * 32 + lkq * 16) ^ lsw);
                uint32_t Ah[4];
                ldsm4(Ah, base + (uint32_t)((mw * 16 + lrowoff) * 128) + bcol);
#pragma unroll
                for (int nt = 0; nt < 2; nt++) {
                    const uint4 Bv = *(const uint4*)(sm
                        + ((size_t)((nh * 2 + nt) * 2048 + (c * 4 + kl) * 32 + lane)) * 16);
                    mma_hf(acc[nt], Ah, Bv.x, Bv.y);
                    mma_hf(acc[nt], Ah, Bv.z, Bv.w);
                }
            }
            __syncthreads();
            if (c + 2 < 16) load_chunk(c & 1, (c + 2) * 64, g_hfp);
        }

        // phase1 epilogue
#pragma unroll
        for (int nt = 0; nt < 2; nt++) {
#pragma unroll
            for (int hf = 0; hf < 2; hf++) {
                const int b = bbase + mw * 16 + gid + hf * 8;
                const float dx = acc[nt][hf * 2], dy = acc[nt][hf * 2 + 1];
                if (!isR) {
                    float2 zv;
                    zv.x = sigmoidf_(dx + pxg[nt][hf].x);
                    zv.y = sigmoidf_(dy + pxg[nt][hf].y);
                    *(float2*)&g_z[(size_t)b * Hdim + Ncol0 + nt * 8] = zv;
                } else {
                    const int j = jj0 + nt * 8;
                    float r0 = sigmoidf_(dx + pxg[nt][hf].x) * ph2[nt][hf].x;
                    float r1 = sigmoidf_(dy + pxg[nt][hf].y) * ph2[nt][hf].y;
                    g_rhfp[(size_t)b * 512 + (j >> 1)] =
                        packh(__float2half_rn(r0), __float2half_rn(r1));
                }
            }
        }
        grid_sync();

        // ================= phase 2 : candidate + update =================
        float ac2[4] = { 0.f, 0.f, 0.f, 0.f };
        load_chunk(0, 0, g_rhfp);
        load_chunk(1, 64, g_rhfp);

        const int n = ngrp * 16 + nh * 8 + t4 * 2;
        const float* xh = g_xproj + 2 * TBH + (size_t)t * BH;
        float2 pxh[2], pz2[2], phv[2];
#pragma unroll
        for (int hf = 0; hf < 2; hf++) {
            const int b = bbase + mw * 16 + gid + hf * 8;
            pxh[hf] = __ldcs((const float2*)(xh + (size_t)b * Hdim + n));
            pz2[hf] = __ldcg((const float2*)&g_z[(size_t)b * Hdim + n]);
            phv[hf] = __ldcg((const float2*)&g_h[(size_t)b * Hdim + n]);
        }

        for (int c = 0; c < 16; c++) {
            if (c < 15) CP_WAIT1(); else CP_WAIT0();
            __syncthreads();
            const uint32_t base = abase + (c & 1) * 8192;
#pragma unroll
            for (int kl = 0; kl < 4; kl++) {
                const uint32_t bcol = (uint32_t)((kl * 32 + lkq * 16) ^ lsw);
                uint32_t Ah[4];
                ldsm4(Ah, base + (uint32_t)((mw * 16 + lrowoff) * 128) + bcol);
                const uint4 Bv = *(const uint4*)(sm + 131072
                               + ((size_t)(nh * 2048 + (c * 4 + kl) * 32 + lane)) * 16);
                mma_hf(ac2, Ah, Bv.x, Bv.y);
                mma_hf(ac2, Ah, Bv.z, Bv.w);
            }
            __syncthreads();
            if (c + 2 < 16) load_chunk(c & 1, (c + 2) * 64, g_rhfp);
        }

        // phase2 epilogue
#pragma unroll
        for (int hf = 0; hf < 2; hf++) {
            const int b = bbase + mw * 16 + gid + hf * 8;
            float c0 = tanhf(ac2[hf * 2]     + pxh[hf].x);
            float c1 = tanhf(ac2[hf * 2 + 1] + pxh[hf].y);
            float hn0 = phv[hf].x + pz2[hf].x * (c0 - phv[hf].x);
            float hn1 = phv[hf].y + pz2[hf].y * (c1 - phv[hf].y);
            *(float2*)&g_h[(size_t)b * Hdim + n] = make_float2(hn0, hn1);
            g_hfp[(size_t)b * 512 + (n >> 1)] =
                packh(__float2half_rn(hn0), __float2half_rn(hn1));
            if (out)
                *(float2*)&out[(size_t)t * BH + (size_t)b * Hdim + n] = make_float2(hn0, hn1);
        }
        grid_sync();
    }
}

// ---------------- final hidden state ----------------
__global__ void hlast_kernel(float* __restrict__ dst) {
    int i = blockIdx.x * 256 + threadIdx.x;
    dst[i] = g_h[i];
}

// ---------------- launch ----------------
extern "C" void kernel_launch(void* const* d_in, const int* in_sizes, int n_in,
                              void* d_out, int out_size)
{
    (void)in_sizes; (void)n_in;
    const float* x   = (const float*)d_in[0];
    const float* h0  = (const float*)d_in[1];
    const float* Wiu = (const float*)d_in[2];
    const float* Whu = (const float*)d_in[3];
    const float* bu  = (const float*)d_in[4];
    const float* Wir = (const float*)d_in[5];
    const float* Whr = (const float*)d_in[6];
    const float* br  = (const float*)d_in[7];
    const float* Wih = (const float*)d_in[8];
    const float* Whh = (const float*)d_in[9];
    const float* bh  = (const float*)d_in[10];
    float* out = (float*)d_out;

    const bool write_seq  = ((size_t)out_size >= TBH);
    const bool write_last = ((size_t)out_size >= TBH + (size_t)Bsz * Hdim);

    cudaFuncSetAttribute(proj_mma_kernel,
                         cudaFuncAttributeMaxDynamicSharedMemorySize, PROJ_SMEM);
    cudaFuncSetAttribute(gru_rec_kernel,
                         cudaFuncAttributeMaxDynamicSharedMemorySize, REC_SMEM);

    init_h_kernel<<<BH / 512, 256>>>(h0);
    pack_x_kernel<<<65536, 256>>>(x);
    pack_WpF_kernel<<<3072, 256>>>(Wiu, Wir, Wih);
    pack_wzrC_kernel<<<4096, 256>>>(Whu, Whr);
    pack_whhC_kernel<<<2048, 256>>>(Whh);

    dim3 pg(Mrows / 128, 3072 / 128);   // 512 x 24
    proj_mma_kernel<<<pg, 256, PROJ_SMEM>>>(bu, br, bh);

    gru_rec_kernel<<<NC, NT, REC_SMEM>>>(write_seq ? out : nullptr);

    if (write_last)        hlast_kernel<<<BH / 256, 256>>>(out + TBH);
    else if (!write_seq)   hlast_kernel<<<BH / 256, 256>>>(out);
}

// round 10
// speedup vs baseline: 7.2110x; 1.2912x over previous
#include <cuda_runtime.h>
#include <cuda_fp16.h>
#include <cstdint>

#define Bsz  128
#define Tseq 512
#define Din  512
#define Hdim 1024
#define BH   (Bsz * Hdim)
#define TBH  ((size_t)Tseq * (size_t)Bsz * (size_t)Hdim)
#define NC   128
#define NT   256
#define Mrows 65536            // B*T

// ---------------- static device scratch ----------------
__device__ float g_xproj[3ULL * 512ULL * 128ULL * 1024ULL]; // (gate, t, b, h)
__device__ float g_h[BH];                 // h fp32, [b][k]
__device__ float g_z[BH];                 // z gate fp32, [b][n]
__device__ uint32_t g_hfp [BH / 2];       // h  fp16 packed pairs [b][k/2]
__device__ uint32_t g_rhfp[BH / 2];       // r*h fp16 packed pairs
__device__ uint32_t g_xh[(size_t)Mrows * (Din / 2)];   // x fp16 packed pairs (proj A)
__device__ uint32_t g_WzrS[256][64][32][2];     // rec B-frags fp16 single [ntile][k16][lane][reg]
__device__ uint32_t g_WhhS[128][64][32][2];
__device__ uint32_t g_WpF2[2][384][8][32][8];   // proj B-frags fp16 hi/lo
__device__ unsigned int g_bar = 0;

// ---------------- helpers ----------------
__device__ __forceinline__ float sigmoidf_(float x) { return 1.0f / (1.0f + __expf(-x)); }

__device__ __forceinline__ void hsplit(float v, __half& hi, __half& lo) {
    hi = __float2half_rn(v);
    lo = __float2half_rn(v - __half2float(hi));
}
__device__ __forceinline__ uint32_t packh(__half a, __half b) {
    __half2 h2 = __halves2half2(a, b);
    return *(uint32_t*)&h2;
}

__device__ __forceinline__ void cp16(uint32_t s, const void* g) {
    asm volatile("cp.async.cg.shared.global [%0], [%1], 16;" :: "r"(s), "l"(g));
}
#define CP_COMMIT() asm volatile("cp.async.commit_group;")
#define CP_WAIT0()  asm volatile("cp.async.wait_group 0;")
#define CP_WAIT1()  asm volatile("cp.async.wait_group 1;")
#define CP_WAIT2()  asm volatile("cp.async.wait_group 2;")

__device__ __forceinline__ void grid_sync() {
    __syncthreads();
    if (threadIdx.x == 0) {
        __threadfence();
        unsigned int old = atomicAdd(&g_bar, 1u);
        unsigned int target = (old / NC + 1u) * NC;
        unsigned int v;
        do {
            asm volatile("ld.acquire.gpu.global.u32 %0, [%1];"
                         : "=r"(v) : "l"(&g_bar) : "memory");
        } while (v < target);
    }
    __syncthreads();
}

__device__ __forceinline__ void ldsm4(uint32_t (&r)[4], uint32_t a) {
    asm volatile("ldmatrix.sync.aligned.m8n8.x4.shared.b16 {%0,%1,%2,%3}, [%4];"
                 : "=r"(r[0]), "=r"(r[1]), "=r"(r[2]), "=r"(r[3]) : "r"(a));
}
__device__ __forceinline__ void mma_hf(float (&d)[4], const uint32_t (&a)[4],
                                       uint32_t b0, uint32_t b1) {
    asm volatile(
        "mma.sync.aligned.m16n8k16.row.col.f32.f16.f16.f32 "
        "{%0,%1,%2,%3}, {%4,%5,%6,%7}, {%8,%9}, {%0,%1,%2,%3};"
        : "+f"(d[0]), "+f"(d[1]), "+f"(d[2]), "+f"(d[3])
        : "r"(a[0]), "r"(a[1]), "r"(a[2]), "r"(a[3]), "r"(b0), "r"(b1));
}

// ---------------- setup kernels ----------------
__global__ void init_h_kernel(const float* __restrict__ h0) {
    int i = blockIdx.x * 256 + threadIdx.x;        // BH/2
    int b = i >> 9, kp = i & 511;
    float2 v = *(const float2*)&h0[(size_t)b * Hdim + kp * 2];
    *(float2*)&g_h[(size_t)b * Hdim + kp * 2] = v;
    g_hfp[(size_t)b * 512 + kp] = packh(__float2half_rn(v.x), __float2half_rn(v.y));
}

__global__ void pack_x_kernel(const float* __restrict__ x) {
    size_t i = (size_t)blockIdx.x * 256 + threadIdx.x;   // Mrows*Din/2
    float2 v = *(const float2*)&x[i * 2];
    g_xh[i] = packh(__float2half_rn(v.x), __float2half_rn(v.y));
}

__global__ void pack_WpF2_kernel(const float* __restrict__ Wiu, const float* __restrict__ Wir,
                                 const float* __restrict__ Wih) {
    int i = blockIdx.x * 256 + threadIdx.x;        // 786,432
    int e = i & 7, lane = (i >> 3) & 31, kc = (i >> 8) & 7, nt = i >> 11;
    int kl = e >> 1, reg = e & 1;
    int n = nt * 8 + (lane >> 2);
    int gate = n >> 10, nn = n & (Hdim - 1);
    const float* W = (gate == 0) ? Wiu : (gate == 1 ? Wir : Wih);
    int k = kc * 64 + kl * 16 + reg * 8 + (lane & 3) * 2;
    float v0 = W[(size_t)k * Hdim + nn];
    float v1 = W[(size_t)(k + 1) * Hdim + nn];
    __half h0a, l0a, h1a, l1a;
    hsplit(v0, h0a, l0a); hsplit(v1, h1a, l1a);
    g_WpF2[0][nt][kc][lane][e] = packh(h0a, h1a);
    g_WpF2[1][nt][kc][lane][e] = packh(l0a, l1a);
}

__global__ void pack_wzrS_kernel(const float* __restrict__ Whu, const float* __restrict__ Whr) {
    int i = blockIdx.x * 256 + threadIdx.x;        // 1,048,576
    int reg = i & 1, lane = (i >> 1) & 31, k16 = (i >> 6) & 63, nt = i >> 12;
    int n = nt * 8 + (lane >> 2);
    int k = k16 * 16 + reg * 8 + (lane & 3) * 2;
    const float* W = (n < Hdim) ? Whu : Whr;
    int nn = n & (Hdim - 1);
    g_WzrS[nt][k16][lane][reg] =
        packh(__float2half_rn(W[(size_t)k * Hdim + nn]),
              __float2half_rn(W[(size_t)(k + 1) * Hdim + nn]));
}

__global__ void pack_whhS_kernel(const float* __restrict__ Whh) {
    int i = blockIdx.x * 256 + threadIdx.x;        // 524,288
    int reg = i & 1, lane = (i >> 1) & 31, k16 = (i >> 6) & 63, nt = i >> 12;
    int n = nt * 8 + (lane >> 2);
    int k = k16 * 16 + reg * 8 + (lane & 3) * 2;
    g_WhhS[nt][k16][lane][reg] =
        packh(__float2half_rn(Whh[(size_t)k * Hdim + n]),
              __float2half_rn(Whh[(size_t)(k + 1) * Hdim + n]));
}

// ---------------- phase A: tensor-core proj (fp16 A-single / B hi+lo, 2-pass) ----------------
#define PROJ_SMEM (3 * 16384)
__global__ void __launch_bounds__(256) proj_mma_kernel(
    const float* __restrict__ bu, const float* __restrict__ br, const float* __restrict__ bh)
{
    extern __shared__ char sm[];
    const uint32_t smb = (uint32_t)__cvta_generic_to_shared(sm);
    const int tid = threadIdx.x, wid = tid >> 5, lane = tid & 31;
    const int gid = lane >> 2, t4 = lane & 3;
    const int mw = wid & 3, nw = wid >> 2;
    const int rb = blockIdx.x * 128, cb = blockIdx.y * 128;
    const int gate = cb >> 10;
    const float* bias = (gate == 0) ? bu : (gate == 1 ? br : bh);

    const int lrowoff = ((lane >> 3) & 1) * 8 + (lane & 7);
    const int lkq = lane >> 4;
    const int lsw = (lane & 7) * 16;

    float acc[2][8][4];
#pragma unroll
    for (int mt = 0; mt < 2; mt++)
#pragma unroll
        for (int nt = 0; nt < 8; nt++)
#pragma unroll
            for (int i = 0; i < 4; i++) acc[mt][nt][i] = 0.f;

    auto load_chunk = [&](int st, int kc) {
#pragma unroll
        for (int q = 0; q < 4; q++) {
            int u = tid + q * 256;          // 0..1023
            int row = u >> 3, cu = u & 7;
            uint32_t dst = smb + st * 16384 + row * 128
                         + ((cu * 16) ^ ((row & 7) * 16));
            cp16(dst, g_xh + (size_t)(rb + row) * 256 + kc * 32 + cu * 4);
        }
        CP_COMMIT();
    };

    load_chunk(0, 0); load_chunk(1, 1); load_chunk(2, 2);
    for (int c = 0; c < 8; c++) {
        if (c <= 5)      CP_WAIT2();
        else if (c == 6) CP_WAIT1();
        else             CP_WAIT0();
        __syncthreads();
        const uint32_t base = smb + (c % 3) * 16384;
#pragma unroll
        for (int kl = 0; kl < 4; kl++) {
            const uint32_t bcol = (uint32_t)((kl * 32 + lkq * 16) ^ lsw);
            uint32_t Ah[2][4];
#pragma unroll
            for (int mt = 0; mt < 2; mt++) {
                const int mtile = mw * 2 + mt;
                ldsm4(Ah[mt], base + (uint32_t)((mtile * 16 + lrowoff) * 128) + bcol);
            }
#pragma unroll
            for (int nt = 0; nt < 8; nt++) {
                const int ntile = blockIdx.y * 16 + nw * 8 + nt;
                unsigned long long bhp = *(const unsigned long long*)&g_WpF2[0][ntile][c][lane][kl * 2];
                unsigned long long blp = *(const unsigned long long*)&g_WpF2[1][ntile][c][lane][kl * 2];
                const uint32_t bh0 = (uint32_t)bhp, bh1 = (uint32_t)(bhp >> 32);
                const uint32_t bl0 = (uint32_t)blp, bl1 = (uint32_t)(blp >> 32);
#pragma unroll
                for (int mt = 0; mt < 2; mt++) {
                    mma_hf(acc[mt][nt], Ah[mt], bh0, bh1);
                    mma_hf(acc[mt][nt], Ah[mt], bl0, bl1);
                }
            }
        }
        __syncthreads();
        if (c + 3 < 8) load_chunk(c % 3, c + 3);
    }

    float* gout = g_xproj + (size_t)gate * TBH;
#pragma unroll
    for (int nt = 0; nt < 8; nt++) {
        const int ncol = cb + nw * 64 + nt * 8 + t4 * 2;
        const int nn = ncol & (Hdim - 1);
        const float2 bv = *(const float2*)&bias[nn];
#pragma unroll
        for (int mt = 0; mt < 2; mt++) {
#pragma unroll
            for (int hf = 0; hf < 2; hf++) {
                const int m = rb + mw * 32 + mt * 16 + gid + hf * 8;
                const int t = m & (Tseq - 1), bb = m >> 9;
                float2 v;
                v.x = acc[mt][nt][hf * 2]     + bv.x;
                v.y = acc[mt][nt][hf * 2 + 1] + bv.y;
                *(float2*)&gout[((size_t)(t * Bsz + bb)) * Hdim + nn] = v;
            }
        }
    }
}

// ---------------- persistent recurrence: fp16 A + fp16 single-B, k-chunk 256 ----------------
// smem: [0,65536) Wzr frags (4 ntiles x 16KB) | [65536,98304) Whh frags (2 x 16KB)
//       [98304, 163840) A stages 2 x 32 KB (each: 4 sub-blocks of 64 rows x 128B SW128)
#define REC_SMEM 163840
__global__ void __launch_bounds__(NT, 1) gru_rec_kernel(float* __restrict__ out)
{
    extern __shared__ char sm[];
    const uint32_t smb = (uint32_t)__cvta_generic_to_shared(sm);
    const uint32_t abase = smb + 98304;

    const int tid  = threadIdx.x, cta = blockIdx.x;
    const int wid  = tid >> 5, lane = tid & 31;
    const int gid  = lane >> 2, t4 = lane & 3;
    const int bhalf = cta & 1, bbase = bhalf * 64;
    const int ngrp  = cta >> 1;            // 0..63
    const int isR   = ngrp >= 32;

    // warp tiling: 4 mtiles (mw) x 2 n-halves (nh)
    const int mw = wid & 3, nh = wid >> 2;

    const int lrowoff = ((lane >> 3) & 1) * 8 + (lane & 7);
    const int lkq  = lane >> 4;
    const int lsw  = (lane & 7) * 16;

    // ---- preload this CTA's weight fragments into smem (once) ----
    {
        const char* s1 = (const char*)g_WzrS + (size_t)(ngrp * 4) * 16384;
#pragma unroll
        for (int q = 0; q < 16; q++)
            cp16(smb + (uint32_t)(tid + q * NT) * 16, s1 + (size_t)(tid + q * NT) * 16);
        const char* s2 = (const char*)g_WhhS + (size_t)(ngrp * 2) * 16384;
#pragma unroll
        for (int q = 0; q < 8; q++)
            cp16(smb + 65536 + (uint32_t)(tid + q * NT) * 16, s2 + (size_t)(tid + q * NT) * 16);
        CP_COMMIT();
        CP_WAIT0();
        __syncthreads();
    }

    // A chunk: 64 rows x 256 k fp16 = 32 KB per stage (4 sub-blocks of 8 KB)
    auto load_chunk = [&](int st, int k0, const uint32_t* s) {
#pragma unroll
        for (int q = 0; q < 8; q++) {
            int u = tid + q * NT;            // 0..2047
            int sub = u >> 9, rem = u & 511;
            int row = rem >> 3, cu = rem & 7;
            uint32_t dst = abase + st * 32768 + sub * 8192 + row * 128
                         + ((cu * 16) ^ ((row & 7) * 16));
            cp16(dst, s + (size_t)(bbase + row) * 512 + (k0 >> 1) + sub * 32 + cu * 4);
        }
        CP_COMMIT();
    };

    for (int t = 0; t < Tseq; t++) {
        // ================= phase 1 : z / r =================
        float acc[2][4];
#pragma unroll
        for (int nt = 0; nt < 2; nt++)
#pragma unroll
            for (int i = 0; i < 4; i++) acc[nt][i] = 0.f;

        load_chunk(0, 0, g_hfp);
        load_chunk(1, 256, g_hfp);

        // prefetch epilogue operands
        const int Ncol0 = ngrp * 32 + nh * 16 + t4 * 2;     // + nt*8
        const int jj0 = isR ? (Ncol0 - Hdim) : Ncol0;
        const float* xg = g_xproj + (isR ? TBH : (size_t)0) + (size_t)t * BH;
        float2 pxg[2][2], ph2[2][2];
#pragma unroll
        for (int nt = 0; nt < 2; nt++)
#pragma unroll
            for (int hf = 0; hf < 2; hf++) {
                const int b = bbase + mw * 16 + gid + hf * 8;
                pxg[nt][hf] = __ldcs((const float2*)(xg + (size_t)b * Hdim + jj0 + nt * 8));
                if (isR) ph2[nt][hf] = __ldcg((const float2*)&g_h[(size_t)b * Hdim + jj0 + nt * 8]);
            }

        for (int c = 0; c < 4; c++) {
            if (c < 3) CP_WAIT1(); else CP_WAIT0();
            __syncthreads();
            const uint32_t base = abase + (c & 1) * 32768;
#pragma unroll
            for (int kl = 0; kl < 16; kl++) {
                const uint32_t asub = base + (kl >> 2) * 8192;
                const uint32_t bcol = (uint32_t)(((kl & 3) * 32 + lkq * 16) ^ lsw);
                uint32_t Ah[4];
                ldsm4(Ah, asub + (uint32_t)((mw * 16 + lrowoff) * 128) + bcol);
#pragma unroll
                for (int nt = 0; nt < 2; nt++) {
                    const uint2 Bv = *(const uint2*)(sm
                        + (size_t)((nh * 2 + nt) * 16384 + (c * 16 + kl) * 256 + lane * 8));
                    mma_hf(acc[nt], Ah, Bv.x, Bv.y);
                }
            }
            __syncthreads();
            if (c + 2 < 4) load_chunk(c & 1, (c + 2) * 256, g_hfp);
        }

        // phase1 epilogue
#pragma unroll
        for (int nt = 0; nt < 2; nt++) {
#pragma unroll
            for (int hf = 0; hf < 2; hf++) {
                const int b = bbase + mw * 16 + gid + hf * 8;
                const float dx = acc[nt][hf * 2], dy = acc[nt][hf * 2 + 1];
                if (!isR) {
                    float2 zv;
                    zv.x = sigmoidf_(dx + pxg[nt][hf].x);
                    zv.y = sigmoidf_(dy + pxg[nt][hf].y);
                    *(float2*)&g_z[(size_t)b * Hdim + Ncol0 + nt * 8] = zv;
                } else {
                    const int j = jj0 + nt * 8;
                    float r0 = sigmoidf_(dx + pxg[nt][hf].x) * ph2[nt][hf].x;
                    float r1 = sigmoidf_(dy + pxg[nt][hf].y) * ph2[nt][hf].y;
                    g_rhfp[(size_t)b * 512 + (j >> 1)] =
                        packh(__float2half_rn(r0), __float2half_rn(r1));
                }
            }
        }
        grid_sync();

        // ================= phase 2 : candidate + update =================
        float ac2[4] = { 0.f, 0.f, 0.f, 0.f };
        load_chunk(0, 0, g_rhfp);
        load_chunk(1, 256, g_rhfp);

        const int n = ngrp * 16 + nh * 8 + t4 * 2;
        const float* xh = g_xproj + 2 * TBH + (size_t)t * BH;
        float2 pxh[2], pz2[2], phv[2];
#pragma unroll
        for (int hf = 0; hf < 2; hf++) {
            const int b = bbase + mw * 16 + gid + hf * 8;
            pxh[hf] = __ldcs((const float2*)(xh + (size_t)b * Hdim + n));
            pz2[hf] = __ldcg((const float2*)&g_z[(size_t)b * Hdim + n]);
            phv[hf] = __ldcg((const float2*)&g_h[(size_t)b * Hdim + n]);
        }

        for (int c = 0; c < 4; c++) {
            if (c < 3) CP_WAIT1(); else CP_WAIT0();
            __syncthreads();
            const uint32_t base = abase + (c & 1) * 32768;
#pragma unroll
            for (int kl = 0; kl < 16; kl++) {
                const uint32_t asub = base + (kl >> 2) * 8192;
                const uint32_t bcol = (uint32_t)(((kl & 3) * 32 + lkq * 16) ^ lsw);
                uint32_t Ah[4];
                ldsm4(Ah, asub + (uint32_t)((mw * 16 + lrowoff) * 128) + bcol);
                const uint2 Bv = *(const uint2*)(sm
                    + (size_t)(65536 + nh * 16384 + (c * 16 + kl) * 256 + lane * 8));
                mma_hf(ac2, Ah, Bv.x, Bv.y);
            }
            __syncthreads();
            if (c + 2 < 4) load_chunk(c & 1, (c + 2) * 256, g_rhfp);
        }

        // phase2 epilogue
#pragma unroll
        for (int hf = 0; hf < 2; hf++) {
            const int b = bbase + mw * 16 + gid + hf * 8;
            float c0 = tanhf(ac2[hf * 2]     + pxh[hf].x);
            float c1 = tanhf(ac2[hf * 2 + 1] + pxh[hf].y);
            float hn0 = phv[hf].x + pz2[hf].x * (c0 - phv[hf].x);
            float hn1 = phv[hf].y + pz2[hf].y * (c1 - phv[hf].y);
            *(float2*)&g_h[(size_t)b * Hdim + n] = make_float2(hn0, hn1);
            g_hfp[(size_t)b * 512 + (n >> 1)] =
                packh(__float2half_rn(hn0), __float2half_rn(hn1));
            if (out)
                *(float2*)&out[(size_t)t * BH + (size_t)b * Hdim + n] = make_float2(hn0, hn1);
        }
        grid_sync();
    }
}

// ---------------- final hidden state ----------------
__global__ void hlast_kernel(float* __restrict__ dst) {
    int i = blockIdx.x * 256 + threadIdx.x;
    dst[i] = g_h[i];
}

// ---------------- launch ----------------
extern "C" void kernel_launch(void* const* d_in, const int* in_sizes, int n_in,
                              void* d_out, int out_size)
{
    (void)in_sizes; (void)n_in;
    const float* x   = (const float*)d_in[0];
    const float* h0  = (const float*)d_in[1];
    const float* Wiu = (const float*)d_in[2];
    const float* Whu = (const float*)d_in[3];
    const float* bu  = (const float*)d_in[4];
    const float* Wir = (const float*)d_in[5];
    const float* Whr = (const float*)d_in[6];
    const float* br  = (const float*)d_in[7];
    const float* Wih = (const float*)d_in[8];
    const float* Whh = (const float*)d_in[9];
    const float* bh  = (const float*)d_in[10];
    float* out = (float*)d_out;

    const bool write_seq  = ((size_t)out_size >= TBH);
    const bool write_last = ((size_t)out_size >= TBH + (size_t)Bsz * Hdim);

    cudaFuncSetAttribute(proj_mma_kernel,
                         cudaFuncAttributeMaxDynamicSharedMemorySize, PROJ_SMEM);
    cudaFuncSetAttribute(gru_rec_kernel,
                         cudaFuncAttributeMaxDynamicSharedMemorySize, REC_SMEM);

    init_h_kernel<<<BH / 512, 256>>>(h0);
    pack_x_kernel<<<65536, 256>>>(x);
    pack_WpF2_kernel<<<3072, 256>>>(Wiu, Wir, Wih);
    pack_wzrS_kernel<<<4096, 256>>>(Whu, Whr);
    pack_whhS_kernel<<<2048, 256>>>(Whh);

    dim3 pg(Mrows / 128, 3072 / 128);   // 512 x 24
    proj_mma_kernel<<<pg, 256, PROJ_SMEM>>>(bu, br, bh);

    gru_rec_kernel<<<NC, NT, REC_SMEM>>>(write_seq ? out : nullptr);

    if (write_last)        hlast_kernel<<<BH / 256, 256>>>(out + TBH);
    else if (!write_seq)   hlast_kernel<<<BH / 256, 256>>>(out);
}

// round 11
// speedup vs baseline: 7.4087x; 1.0274x over previous
#include <cuda_runtime.h>
#include <cuda_fp16.h>
#include <cstdint>

#define Bsz  128
#define Tseq 512
#define Din  512
#define Hdim 1024
#define BH   (Bsz * Hdim)
#define TBH  ((size_t)Tseq * (size_t)Bsz * (size_t)Hdim)
#define NC   128
#define NT   256
#define Mrows 65536            // B*T

// ---------------- static device scratch ----------------
__device__ float g_xproj[3ULL * 512ULL * 128ULL * 1024ULL]; // (gate, t, b, h)
__device__ float g_h[BH];                 // h fp32, [b][k]
__device__ float g_z[BH];                 // z gate fp32, [b][n]
__device__ uint32_t g_hfp [BH / 2];       // h  fp16 packed pairs [b][k/2]
__device__ uint32_t g_rhfp[BH / 2];       // r*h fp16 packed pairs
__device__ uint32_t g_xh[(size_t)Mrows * (Din / 2)];   // x fp16 packed pairs (proj A)
__device__ uint32_t g_WzrS[256][64][32][2];     // rec B-frags fp16 single [ntile][k16][lane][reg]
__device__ uint32_t g_WhhS[128][64][32][2];
__device__ uint32_t g_WpF2[2][384][8][32][8];   // proj B-frags fp16 hi/lo
__device__ unsigned int g_bar = 0;

// ---------------- helpers ----------------
__device__ __forceinline__ float sigmoidf_(float x) { return 1.0f / (1.0f + __expf(-x)); }

__device__ __forceinline__ void hsplit(float v, __half& hi, __half& lo) {
    hi = __float2half_rn(v);
    lo = __float2half_rn(v - __half2float(hi));
}
__device__ __forceinline__ uint32_t packh(__half a, __half b) {
    __half2 h2 = __halves2half2(a, b);
    return *(uint32_t*)&h2;
}

__device__ __forceinline__ void cp16(uint32_t s, const void* g) {
    asm volatile("cp.async.cg.shared.global [%0], [%1], 16;" :: "r"(s), "l"(g));
}
#define CP_COMMIT() asm volatile("cp.async.commit_group;")
#define CP_WAIT0()  asm volatile("cp.async.wait_group 0;")
#define CP_WAIT1()  asm volatile("cp.async.wait_group 1;")
#define CP_WAIT2()  asm volatile("cp.async.wait_group 2;")
#define CP_WAIT3()  asm volatile("cp.async.wait_group 3;")

// release-arrive on the grid barrier; returns the generation target
__device__ __forceinline__ unsigned grid_arrive() {
    unsigned old;
    asm volatile("atom.release.gpu.global.add.u32 %0, [%1], 1;"
                 : "=r"(old) : "l"(&g_bar) : "memory");
    return (old / NC + 1u) * NC;
}
__device__ __forceinline__ void grid_wait(unsigned target) {
    unsigned v;
    do {
        asm volatile("ld.acquire.gpu.global.u32 %0, [%1];"
                     : "=r"(v) : "l"(&g_bar) : "memory");
    } while (v < target);
}
__device__ __forceinline__ void grid_sync() {
    __syncthreads();
    if (threadIdx.x == 0) grid_wait(grid_arrive());
    __syncthreads();
}

__device__ __forceinline__ void ldsm4(uint32_t (&r)[4], uint32_t a) {
    asm volatile("ldmatrix.sync.aligned.m8n8.x4.shared.b16 {%0,%1,%2,%3}, [%4];"
                 : "=r"(r[0]), "=r"(r[1]), "=r"(r[2]), "=r"(r[3]) : "r"(a));
}
__device__ __forceinline__ void mma_hf(float (&d)[4], const uint32_t (&a)[4],
                                       uint32_t b0, uint32_t b1) {
    asm volatile(
        "mma.sync.aligned.m16n8k16.row.col.f32.f16.f16.f32 "
        "{%0,%1,%2,%3}, {%4,%5,%6,%7}, {%8,%9}, {%0,%1,%2,%3};"
        : "+f"(d[0]), "+f"(d[1]), "+f"(d[2]), "+f"(d[3])
        : "r"(a[0]), "r"(a[1]), "r"(a[2]), "r"(a[3]), "r"(b0), "r"(b1));
}

// ---------------- setup kernels ----------------
__global__ void init_h_kernel(const float* __restrict__ h0) {
    int i = blockIdx.x * 256 + threadIdx.x;        // BH/2
    int b = i >> 9, kp = i & 511;
    float2 v = *(const float2*)&h0[(size_t)b * Hdim + kp * 2];
    *(float2*)&g_h[(size_t)b * Hdim + kp * 2] = v;
    g_hfp[(size_t)b * 512 + kp] = packh(__float2half_rn(v.x), __float2half_rn(v.y));
}

__global__ void pack_x_kernel(const float* __restrict__ x) {
    size_t i = (size_t)blockIdx.x * 256 + threadIdx.x;   // Mrows*Din/2
    float2 v = *(const float2*)&x[i * 2];
    g_xh[i] = packh(__float2half_rn(v.x), __float2half_rn(v.y));
}

__global__ void pack_WpF2_kernel(const float* __restrict__ Wiu, const float* __restrict__ Wir,
                                 const float* __restrict__ Wih) {
    int i = blockIdx.x * 256 + threadIdx.x;        // 786,432
    int e = i & 7, lane = (i >> 3) & 31, kc = (i >> 8) & 7, nt = i >> 11;
    int kl = e >> 1, reg = e & 1;
    int n = nt * 8 + (lane >> 2);
    int gate = n >> 10, nn = n & (Hdim - 1);
    const float* W = (gate == 0) ? Wiu : (gate == 1 ? Wir : Wih);
    int k = kc * 64 + kl * 16 + reg * 8 + (lane & 3) * 2;
    float v0 = W[(size_t)k * Hdim + nn];
    float v1 = W[(size_t)(k + 1) * Hdim + nn];
    __half h0a, l0a, h1a, l1a;
    hsplit(v0, h0a, l0a); hsplit(v1, h1a, l1a);
    g_WpF2[0][nt][kc][lane][e] = packh(h0a, h1a);
    g_WpF2[1][nt][kc][lane][e] = packh(l0a, l1a);
}

__global__ void pack_wzrS_kernel(const float* __restrict__ Whu, const float* __restrict__ Whr) {
    int i = blockIdx.x * 256 + threadIdx.x;        // 1,048,576
    int reg = i & 1, lane = (i >> 1) & 31, k16 = (i >> 6) & 63, nt = i >> 12;
    int n = nt * 8 + (lane >> 2);
    int k = k16 * 16 + reg * 8 + (lane & 3) * 2;
    const float* W = (n < Hdim) ? Whu : Whr;
    int nn = n & (Hdim - 1);
    g_WzrS[nt][k16][lane][reg] =
        packh(__float2half_rn(W[(size_t)k * Hdim + nn]),
              __float2half_rn(W[(size_t)(k + 1) * Hdim + nn]));
}

__global__ void pack_whhS_kernel(const float* __restrict__ Whh) {
    int i = blockIdx.x * 256 + threadIdx.x;        // 524,288
    int reg = i & 1, lane = (i >> 1) & 31, k16 = (i >> 6) & 63, nt = i >> 12;
    int n = nt * 8 + (lane >> 2);
    int k = k16 * 16 + reg * 8 + (lane & 3) * 2;
    g_WhhS[nt][k16][lane][reg] =
        packh(__float2half_rn(Whh[(size_t)k * Hdim + n]),
              __float2half_rn(Whh[(size_t)(k + 1) * Hdim + n]));
}

// ---------------- phase A: tensor-core proj (fp16 A-single / B hi+lo, 2-pass) ----------------
#define PROJ_SMEM (3 * 16384)
__global__ void __launch_bounds__(256) proj_mma_kernel(
    const float* __restrict__ bu, const float* __restrict__ br, const float* __restrict__ bh)
{
    extern __shared__ char sm[];
    const uint32_t smb = (uint32_t)__cvta_generic_to_shared(sm);
    const int tid = threadIdx.x, wid = tid >> 5, lane = tid & 31;
    const int gid = lane >> 2, t4 = lane & 3;
    const int mw = wid & 3, nw = wid >> 2;
    const int rb = blockIdx.x * 128, cb = blockIdx.y * 128;
    const int gate = cb >> 10;
    const float* bias = (gate == 0) ? bu : (gate == 1 ? br : bh);

    const int lrowoff = ((lane >> 3) & 1) * 8 + (lane & 7);
    const int lkq = lane >> 4;
    const int lsw = (lane & 7) * 16;

    float acc[2][8][4];
#pragma unroll
    for (int mt = 0; mt < 2; mt++)
#pragma unroll
        for (int nt = 0; nt < 8; nt++)
#pragma unroll
            for (int i = 0; i < 4; i++) acc[mt][nt][i] = 0.f;

    auto load_chunk = [&](int st, int kc) {
#pragma unroll
        for (int q = 0; q < 4; q++) {
            int u = tid + q * 256;          // 0..1023
            int row = u >> 3, cu = u & 7;
            uint32_t dst = smb + st * 16384 + row * 128
                         + ((cu * 16) ^ ((row & 7) * 16));
            cp16(dst, g_xh + (size_t)(rb + row) * 256 + kc * 32 + cu * 4);
        }
        CP_COMMIT();
    };

    load_chunk(0, 0); load_chunk(1, 1); load_chunk(2, 2);
    for (int c = 0; c < 8; c++) {
        if (c <= 5)      CP_WAIT2();
        else if (c == 6) CP_WAIT1();
        else             CP_WAIT0();
        __syncthreads();
        const uint32_t base = smb + (c % 3) * 16384;
#pragma unroll
        for (int kl = 0; kl < 4; kl++) {
            const uint32_t bcol = (uint32_t)((kl * 32 + lkq * 16) ^ lsw);
            uint32_t Ah[2][4];
#pragma unroll
            for (int mt = 0; mt < 2; mt++) {
                const int mtile = mw * 2 + mt;
                ldsm4(Ah[mt], base + (uint32_t)((mtile * 16 + lrowoff) * 128) + bcol);
            }
#pragma unroll
            for (int nt = 0; nt < 8; nt++) {
                const int ntile = blockIdx.y * 16 + nw * 8 + nt;
                unsigned long long bhp = *(const unsigned long long*)&g_WpF2[0][ntile][c][lane][kl * 2];
                unsigned long long blp = *(const unsigned long long*)&g_WpF2[1][ntile][c][lane][kl * 2];
                const uint32_t bh0 = (uint32_t)bhp, bh1 = (uint32_t)(bhp >> 32);
                const uint32_t bl0 = (uint32_t)blp, bl1 = (uint32_t)(blp >> 32);
#pragma unroll
                for (int mt = 0; mt < 2; mt++) {
                    mma_hf(acc[mt][nt], Ah[mt], bh0, bh1);
                    mma_hf(acc[mt][nt], Ah[mt], bl0, bl1);
                }
            }
        }
        __syncthreads();
        if (c + 3 < 8) load_chunk(c % 3, c + 3);
    }

    float* gout = g_xproj + (size_t)gate * TBH;
#pragma unroll
    for (int nt = 0; nt < 8; nt++) {
        const int ncol = cb + nw * 64 + nt * 8 + t4 * 2;
        const int nn = ncol & (Hdim - 1);
        const float2 bv = *(const float2*)&bias[nn];
#pragma unroll
        for (int mt = 0; mt < 2; mt++) {
#pragma unroll
            for (int hf = 0; hf < 2; hf++) {
                const int m = rb + mw * 32 + mt * 16 + gid + hf * 8;
                const int t = m & (Tseq - 1), bb = m >> 9;
                float2 v;
                v.x = acc[mt][nt][hf * 2]     + bv.x;
                v.y = acc[mt][nt][hf * 2 + 1] + bv.y;
                *(float2*)&gout[((size_t)(t * Bsz + bb)) * Hdim + nn] = v;
            }
        }
    }
}

// ---------------- persistent recurrence: A-resident phases, fp16 single ----------------
// smem: [0,65536) Wzr frags (4 ntiles x 16KB) | [65536,98304) Whh frags (2 x 16KB)
//       [98304, 229376) A panel: 16 sub-blocks of (64 rows x 64 k fp16, SW128) = 128 KB
#define REC_SMEM 229376
__global__ void __launch_bounds__(NT, 1) gru_rec_kernel(float* __restrict__ out)
{
    extern __shared__ char sm[];
    const uint32_t smb = (uint32_t)__cvta_generic_to_shared(sm);
    const uint32_t abase = smb + 98304;

    const int tid  = threadIdx.x, cta = blockIdx.x;
    const int wid  = tid >> 5, lane = tid & 31;
    const int gid  = lane >> 2, t4 = lane & 3;
    const int bhalf = cta & 1, bbase = bhalf * 64;
    const int ngrp  = cta >> 1;            // 0..63
    const int isR   = ngrp >= 32;

    // warp tiling: 4 mtiles (mw) x 2 n-halves (nh)
    const int mw = wid & 3, nh = wid >> 2;

    const int lrowoff = ((lane >> 3) & 1) * 8 + (lane & 7);
    const int lkq  = lane >> 4;
    const int lsw  = (lane & 7) * 16;

    // ---- preload this CTA's weight fragments into smem (once) ----
    {
        const char* s1 = (const char*)g_WzrS + (size_t)(ngrp * 4) * 16384;
#pragma unroll
        for (int q = 0; q < 16; q++)
            cp16(smb + (uint32_t)(tid + q * NT) * 16, s1 + (size_t)(tid + q * NT) * 16);
        const char* s2 = (const char*)g_WhhS + (size_t)(ngrp * 2) * 16384;
#pragma unroll
        for (int q = 0; q < 8; q++)
            cp16(smb + 65536 + (uint32_t)(tid + q * NT) * 16, s2 + (size_t)(tid + q * NT) * 16);
        CP_COMMIT();
        CP_WAIT0();
        __syncthreads();
    }

    // Issue the FULL 128 KB A panel in 4 commit groups (group g = k range [g*256, g*256+256))
    auto load_A = [&](const uint32_t* s) {
#pragma unroll
        for (int g = 0; g < 4; g++) {
#pragma unroll
            for (int q = 0; q < 8; q++) {
                int u = tid + q * NT;            // 0..2047
                int sub = u >> 9, rem = u & 511;
                int row = rem >> 3, cu = rem & 7;
                uint32_t dst = abase + (uint32_t)(g * 4 + sub) * 8192 + row * 128
                             + ((cu * 16) ^ ((row & 7) * 16));
                cp16(dst, s + (size_t)(bbase + row) * 512 + g * 128 + sub * 32 + cu * 4);
            }
            CP_COMMIT();
        }
    };

    for (int t = 0; t < Tseq; t++) {
        // ================= phase 1 : z / r =================
        float acc[2][4];
#pragma unroll
        for (int nt = 0; nt < 2; nt++)
#pragma unroll
            for (int i = 0; i < 4; i++) acc[nt][i] = 0.f;

        load_A(g_hfp);

        // prefetch epilogue operands (latency hidden under MMA loop)
        const int Ncol0 = ngrp * 32 + nh * 16 + t4 * 2;     // + nt*8
        const int jj0 = isR ? (Ncol0 - Hdim) : Ncol0;
        const float* xg = g_xproj + (isR ? TBH : (size_t)0) + (size_t)t * BH;
        float2 pxg[2][2], ph2[2][2];
#pragma unroll
        for (int nt = 0; nt < 2; nt++)
#pragma unroll
            for (int hf = 0; hf < 2; hf++) {
                const int b = bbase + mw * 16 + gid + hf * 8;
                pxg[nt][hf] = __ldcs((const float2*)(xg + (size_t)b * Hdim + jj0 + nt * 8));
                if (isR) ph2[nt][hf] = __ldcg((const float2*)&g_h[(size_t)b * Hdim + jj0 + nt * 8]);
            }

#pragma unroll
        for (int g = 0; g < 4; g++) {
            if (g == 0)      CP_WAIT3();
            else if (g == 1) CP_WAIT2();
            else if (g == 2) CP_WAIT1();
            else             CP_WAIT0();
            __syncthreads();
#pragma unroll
            for (int kl = 0; kl < 16; kl++) {
                const int kk = g * 16 + kl;
                const uint32_t asub = abase + (uint32_t)(kk >> 2) * 8192;
                const uint32_t bcol = (uint32_t)(((kk & 3) * 32 + lkq * 16) ^ lsw);
                uint32_t Ah[4];
                ldsm4(Ah, asub + (uint32_t)((mw * 16 + lrowoff) * 128) + bcol);
#pragma unroll
                for (int nt = 0; nt < 2; nt++) {
                    const uint2 Bv = *(const uint2*)(sm
                        + (size_t)((nh * 2 + nt) * 16384 + kk * 256 + lane * 8));
                    mma_hf(acc[nt], Ah, Bv.x, Bv.y);
                }
            }
        }

        // phase1 epilogue
#pragma unroll
        for (int nt = 0; nt < 2; nt++) {
#pragma unroll
            for (int hf = 0; hf < 2; hf++) {
                const int b = bbase + mw * 16 + gid + hf * 8;
                const float dx = acc[nt][hf * 2], dy = acc[nt][hf * 2 + 1];
                if (!isR) {
                    float2 zv;
                    zv.x = sigmoidf_(dx + pxg[nt][hf].x);
                    zv.y = sigmoidf_(dy + pxg[nt][hf].y);
                    *(float2*)&g_z[(size_t)b * Hdim + Ncol0 + nt * 8] = zv;
                } else {
                    const int j = jj0 + nt * 8;
                    float r0 = sigmoidf_(dx + pxg[nt][hf].x) * ph2[nt][hf].x;
                    float r1 = sigmoidf_(dy + pxg[nt][hf].y) * ph2[nt][hf].y;
                    g_rhfp[(size_t)b * 512 + (j >> 1)] =
                        packh(__float2half_rn(r0), __float2half_rn(r1));
                }
            }
        }
        grid_sync();

        // ================= phase 2 : candidate + update =================
        float ac2[4] = { 0.f, 0.f, 0.f, 0.f };
        load_A(g_rhfp);

        const int n = ngrp * 16 + nh * 8 + t4 * 2;
        const float* xh = g_xproj + 2 * TBH + (size_t)t * BH;
        float2 pxh[2], pz2[2], phv[2];
#pragma unroll
        for (int hf = 0; hf < 2; hf++) {
            const int b = bbase + mw * 16 + gid + hf * 8;
            pxh[hf] = __ldcs((const float2*)(xh + (size_t)b * Hdim + n));
            pz2[hf] = __ldcg((const float2*)&g_z[(size_t)b * Hdim + n]);
            phv[hf] = __ldcg((const float2*)&g_h[(size_t)b * Hdim + n]);
        }

#pragma unroll
        for (int g = 0; g < 4; g++) {
            if (g == 0)      CP_WAIT3();
            else if (g == 1) CP_WAIT2();
            else if (g == 2) CP_WAIT1();
            else             CP_WAIT0();
            __syncthreads();
#pragma unroll
            for (int kl = 0; kl < 16; kl++) {
                const int kk = g * 16 + kl;
                const uint32_t asub = abase + (uint32_t)(kk >> 2) * 8192;
                const uint32_t bcol = (uint32_t)(((kk & 3) * 32 + lkq * 16) ^ lsw);
                uint32_t Ah[4];
                ldsm4(Ah, asub + (uint32_t)((mw * 16 + lrowoff) * 128) + bcol);
                const uint2 Bv = *(const uint2*)(sm
                    + (size_t)(65536 + nh * 16384 + kk * 256 + lane * 8));
                mma_hf(ac2, Ah, Bv.x, Bv.y);
            }
        }

        // phase2 epilogue: write h state, arrive, then out-store overlaps the barrier wait
        float hn[2][2];
#pragma unroll
        for (int hf = 0; hf < 2; hf++) {
            const int b = bbase + mw * 16 + gid + hf * 8;
            float c0 = tanhf(ac2[hf * 2]     + pxh[hf].x);
            float c1 = tanhf(ac2[hf * 2 + 1] + pxh[hf].y);
            hn[hf][0] = phv[hf].x + pz2[hf].x * (c0 - phv[hf].x);
            hn[hf][1] = phv[hf].y + pz2[hf].y * (c1 - phv[hf].y);
            *(float2*)&g_h[(size_t)b * Hdim + n] = make_float2(hn[hf][0], hn[hf][1]);
            g_hfp[(size_t)b * 512 + (n >> 1)] =
                packh(__float2half_rn(hn[hf][0]), __float2half_rn(hn[hf][1]));
        }
        __syncthreads();
        unsigned target = 0;
        if (tid == 0) target = grid_arrive();
        if (out) {
#pragma unroll
            for (int hf = 0; hf < 2; hf++) {
                const int b = bbase + mw * 16 + gid + hf * 8;
                *(float2*)&out[(size_t)t * BH + (size_t)b * Hdim + n] =
                    make_float2(hn[hf][0], hn[hf][1]);
            }
        }
        if (tid == 0) grid_wait(target);
        __syncthreads();
    }
}

// ---------------- final hidden state ----------------
__global__ void hlast_kernel(float* __restrict__ dst) {
    int i = blockIdx.x * 256 + threadIdx.x;
    dst[i] = g_h[i];
}

// ---------------- launch ----------------
extern "C" void kernel_launch(void* const* d_in, const int* in_sizes, int n_in,
                              void* d_out, int out_size)
{
    (void)in_sizes; (void)n_in;
    const float* x   = (const float*)d_in[0];
    const float* h0  = (const float*)d_in[1];
    const float* Wiu = (const float*)d_in[2];
    const float* Whu = (const float*)d_in[3];
    const float* bu  = (const float*)d_in[4];
    const float* Wir = (const float*)d_in[5];
    const float* Whr = (const float*)d_in[6];
    const float* br  = (const float*)d_in[7];
    const float* Wih = (const float*)d_in[8];
    const float* Whh = (const float*)d_in[9];
    const float* bh  = (const float*)d_in[10];
    float* out = (float*)d_out;

    const bool write_seq  = ((size_t)out_size >= TBH);
    const bool write_last = ((size_t)out_size >= TBH + (size_t)Bsz * Hdim);

    cudaFuncSetAttribute(proj_mma_kernel,
                         cudaFuncAttributeMaxDynamicSharedMemorySize, PROJ_SMEM);
    cudaFuncSetAttribute(gru_rec_kernel,
                         cudaFuncAttributeMaxDynamicSharedMemorySize, REC_SMEM);

    init_h_kernel<<<BH / 512, 256>>>(h0);
    pack_x_kernel<<<65536, 256>>>(x);
    pack_WpF2_kernel<<<3072, 256>>>(Wiu, Wir, Wih);
    pack_wzrS_kernel<<<4096, 256>>>(Whu, Whr);
    pack_whhS_kernel<<<2048, 256>>>(Whh);

    dim3 pg(Mrows / 128, 3072 / 128);   // 512 x 24
    proj_mma_kernel<<<pg, 256, PROJ_SMEM>>>(bu, br, bh);

    gru_rec_kernel<<<NC, NT, REC_SMEM>>>(write_seq ? out : nullptr);

    if (write_last)        hlast_kernel<<<BH / 256, 256>>>(out + TBH);
    else if (!write_seq)   hlast_kernel<<<BH / 256, 256>>>(out);
}